// round 5
// baseline (speedup 1.0000x reference)
#include <cuda_runtime.h>
#include <cuda_bf16.h>
#include <cstdint>

#define DH     256
#define NLAY   4
#define NGR    64
#define NTMAX  60160
#define EMAX   960000
#define BNEPS  1e-5f

// ---------------- scratch (static __device__ globals; no allocations) ----------------
__device__ float g_X [NTMAX*128];
__device__ float g_H [NTMAX*DH];
__device__ float g_T0[NTMAX*DH];
__device__ float g_T1[NTMAX*DH];
__device__ float g_stats[4*DH];     // [graph][sum/sumsq][DH]
__device__ float g_scale[2*DH];
__device__ float g_shift[2*DH];
__device__ float g_read[2*NGR*DH];
__device__ int   g_cnt [NTMAX];
__device__ int   g_wofs[NTMAX];
__device__ int   g_rowptr[NTMAX+1];
__device__ int   g_esrc[EMAX];

// ---------------- small utility kernels ----------------
__global__ void zero_kernel(float* p, int n) {
    int i = blockIdx.x * blockDim.x + threadIdx.x;
    if (i < n) p[i] = 0.f;
}
__global__ void zeroi_kernel(int* p, int n) {
    int i = blockIdx.x * blockDim.x + threadIdx.x;
    if (i < n) p[i] = 0;
}

// ================= CSR build (by dst, combined over both graphs) =================
__global__ void hist_k(const int* __restrict__ dst, int E, int* __restrict__ cnt, int off) {
    int i = blockIdx.x * blockDim.x + threadIdx.x;
    if (i < E) atomicAdd(&cnt[dst[i] + off], 1);
}

__global__ void scan_k(const int* __restrict__ cnt, int* __restrict__ rowptr,
                       int* __restrict__ wofs, int N, int E) {
    __shared__ int part[1024];
    int t = threadIdx.x;
    int chunk = (N + 1023) >> 10;
    int b0 = t * chunk, b1 = min(N, b0 + chunk);
    int s = 0;
    for (int b = b0; b < b1; b++) s += cnt[b];
    part[t] = s;
    __syncthreads();
    for (int off = 1; off < 1024; off <<= 1) {
        int v = (t >= off) ? part[t - off] : 0;
        __syncthreads();
        part[t] += v;
        __syncthreads();
    }
    int run = t ? part[t - 1] : 0;
    for (int b = b0; b < b1; b++) {
        rowptr[b] = run; wofs[b] = run; run += cnt[b];
    }
    if (t == 1023) rowptr[N] = E;
}

__global__ void fill_k(const int* __restrict__ src, const int* __restrict__ dst, int E,
                       int* __restrict__ wofs, int* __restrict__ esrc, int off) {
    int i = blockIdx.x * blockDim.x + threadIdx.x;
    if (i < E) {
        int p = atomicAdd(&wofs[dst[i] + off], 1);
        esrc[p] = src[i] + off;
    }
}

// gather: T0[v] = (1+eps[l])*H[v] + sum_{e: dst=v} H[src[e]]   (one warp per node)
__global__ __launch_bounds__(256) void gather_k(
    const float* __restrict__ H, float* __restrict__ out,
    const int* __restrict__ rowptr, const int* __restrict__ esrc,
    const float* __restrict__ eps, int l, int N)
{
    int w    = (blockIdx.x * blockDim.x + threadIdx.x) >> 5;
    int lane = threadIdx.x & 31;
    if (w >= N) return;
    float e = 1.f + __ldg(&eps[l]);
    const float4* hr = (const float4*)(H + (long)w * DH);
    float4 a = hr[lane * 2], b = hr[lane * 2 + 1];
    a.x *= e; a.y *= e; a.z *= e; a.w *= e;
    b.x *= e; b.y *= e; b.z *= e; b.w *= e;
    int i0 = rowptr[w], i1 = rowptr[w + 1];
    for (int i = i0; i < i1; i++) {
        int s = __ldg(&esrc[i]);
        const float4* hs = (const float4*)(H + (long)s * DH);
        float4 u = hs[lane * 2], v = hs[lane * 2 + 1];
        a.x += u.x; a.y += u.y; a.z += u.z; a.w += u.w;
        b.x += v.x; b.y += v.y; b.z += v.z; b.w += v.w;
    }
    float4* o = (float4*)(out + (long)w * DH);
    o[lane * 2] = a; o[lane * 2 + 1] = b;
}

// ================= tensor-core GEMM (split-BF16 x3, software-pipelined) =================
__device__ __forceinline__ uint32_t pack_hi(float e, float o, float& re, float& ro) {
    __nv_bfloat16 he = __float2bfloat16(e);
    __nv_bfloat16 ho = __float2bfloat16(o);
    re = e - __bfloat162float(he);
    ro = o - __bfloat162float(ho);
    return (uint32_t)__bfloat16_as_ushort(he) | ((uint32_t)__bfloat16_as_ushort(ho) << 16);
}
__device__ __forceinline__ uint32_t pack_lo(float re, float ro) {
    __nv_bfloat16 le = __float2bfloat16(re);
    __nv_bfloat16 lo = __float2bfloat16(ro);
    return (uint32_t)__bfloat16_as_ushort(le) | ((uint32_t)__bfloat16_as_ushort(lo) << 16);
}
__device__ __forceinline__ void mma_bf16(float* d, const uint32_t* a, const uint32_t* b) {
    asm volatile("mma.sync.aligned.m16n8k16.row.col.f32.bf16.bf16.f32 "
        "{%0,%1,%2,%3}, {%4,%5,%6,%7}, {%8,%9}, {%0,%1,%2,%3};\n"
        : "+f"(d[0]), "+f"(d[1]), "+f"(d[2]), "+f"(d[3])
        : "r"(a[0]), "r"(a[1]), "r"(a[2]), "r"(a[3]), "r"(b[0]), "r"(b[1]));
}

// C = op_A(A) @ W + bias.  Block tile 128x128, BK=32, 256 thr (8 warps, 64x32 each).
// Rows [0,NG) are graph 0; rows [NGpad,NTOT) are graph 1; blocks never straddle.
template<int K, bool TRANS_A>
__global__ __launch_bounds__(256, 2) void tgemm_k(
    const float* __restrict__ A, const float* __restrict__ W,
    const float* __restrict__ bias, float* __restrict__ C,
    int NG, int NGpad, int NTOT,
    const float* __restrict__ scAll, const float* __restrict__ shAll,
    float* __restrict__ stats)
{
    __shared__ uint32_t AH[128][20];
    __shared__ uint32_t AL[128][20];
    __shared__ uint32_t BH[16][136];
    __shared__ uint32_t BL[16][136];
    __shared__ float sSc[256], sSh[256];

    const int tid  = threadIdx.x;
    const int wid  = tid >> 5, lane = tid & 31;
    const int g    = lane >> 2, tig = lane & 3;
    const int mrw  = (wid & 1) * 64;
    const int nbw  = (wid >> 1) * 32;
    const int mbase = blockIdx.x * 128;
    const int nbase = blockIdx.y * 128;
    const int graph = (mbase >= NGpad) ? 1 : 0;
    const int Mv    = graph ? NTOT : NG;

    if (TRANS_A) {
        sSc[tid] = scAll[graph * DH + tid];
        sSh[tid] = shAll[graph * DH + tid];
        __syncthreads();
    }

    float acc[4][4][4] = {};

    const int ar  = tid >> 1;
    const int akc = (tid & 1) * 16;
    const int bkp = tid >> 4;
    const int bn0 = (tid & 15) * 8;

    const int arow = mbase + ar;
    const bool av  = (arow < NG) || (arow >= NGpad && arow < NTOT);

    float4 aReg[4];
    float4 bE[2], bO[2];

#define LOAD_TILES(KT)                                                          \
    {                                                                           \
        _Pragma("unroll")                                                       \
        for (int j = 0; j < 4; j++)                                             \
            aReg[j] = av ? *(const float4*)&A[(long)arow * K + (KT) + akc + j*4]\
                         : make_float4(0.f, 0.f, 0.f, 0.f);                     \
        const float* We = &W[(long)((KT) + 2 * bkp) * DH + nbase + bn0];        \
        const float* Wo = We + DH;                                              \
        _Pragma("unroll")                                                       \
        for (int j = 0; j < 2; j++) {                                           \
            bE[j] = *(const float4*)(We + j * 4);                               \
            bO[j] = *(const float4*)(Wo + j * 4);                               \
        }                                                                       \
    }

    LOAD_TILES(0);

    for (int kt = 0; kt < K; kt += 32) {
        // ---- convert current regs into hi/lo smem tiles ----
        #pragma unroll
        for (int j = 0; j < 4; j++) {
            int kc = akc + j * 4;
            float x0 = aReg[j].x, x1 = aReg[j].y, x2 = aReg[j].z, x3 = aReg[j].w;
            if (TRANS_A) {
                x0 = fmaxf(fmaf(x0, sSc[kt + kc    ], sSh[kt + kc    ]), 0.f);
                x1 = fmaxf(fmaf(x1, sSc[kt + kc + 1], sSh[kt + kc + 1]), 0.f);
                x2 = fmaxf(fmaf(x2, sSc[kt + kc + 2], sSh[kt + kc + 2]), 0.f);
                x3 = fmaxf(fmaf(x3, sSc[kt + kc + 3], sSh[kt + kc + 3]), 0.f);
            }
            float r0e, r0o, r1e, r1o;
            uint32_t h0 = pack_hi(x0, x1, r0e, r0o);
            uint32_t h1 = pack_hi(x2, x3, r1e, r1o);
            int kp = kc >> 1;
            AH[ar][kp] = h0;  AH[ar][kp + 1] = h1;
            AL[ar][kp] = pack_lo(r0e, r0o);
            AL[ar][kp + 1] = pack_lo(r1e, r1o);
        }
        #pragma unroll
        for (int j = 0; j < 2; j++) {
            float re, ro;
            uint4 h4, l4;
            h4.x = pack_hi(bE[j].x, bO[j].x, re, ro); l4.x = pack_lo(re, ro);
            h4.y = pack_hi(bE[j].y, bO[j].y, re, ro); l4.y = pack_lo(re, ro);
            h4.z = pack_hi(bE[j].z, bO[j].z, re, ro); l4.z = pack_lo(re, ro);
            h4.w = pack_hi(bE[j].w, bO[j].w, re, ro); l4.w = pack_lo(re, ro);
            *(uint4*)&BH[bkp][bn0 + j * 4] = h4;
            *(uint4*)&BL[bkp][bn0 + j * 4] = l4;
        }
        __syncthreads();

        // ---- prefetch next tile into registers (overlaps with mma below) ----
        if (kt + 32 < K) LOAD_TILES(kt + 32);

        // ---- compute: 2 k16 chunks x 4x4 frags x 3 terms ----
        #pragma unroll
        for (int c = 0; c < 2; c++) {
            uint32_t bh[4][2], bl[4][2];
            #pragma unroll
            for (int nf = 0; nf < 4; nf++) {
                int cn = nbw + nf * 8 + g;
                bh[nf][0] = BH[c * 8 + tig][cn];
                bh[nf][1] = BH[c * 8 + tig + 4][cn];
                bl[nf][0] = BL[c * 8 + tig][cn];
                bl[nf][1] = BL[c * 8 + tig + 4][cn];
            }
            #pragma unroll
            for (int mf = 0; mf < 4; mf++) {
                int r0 = mrw + mf * 16 + g;
                uint32_t ah[4], al_[4];
                ah[0] = AH[r0][c * 8 + tig];      ah[1] = AH[r0 + 8][c * 8 + tig];
                ah[2] = AH[r0][c * 8 + tig + 4];  ah[3] = AH[r0 + 8][c * 8 + tig + 4];
                al_[0] = AL[r0][c * 8 + tig];     al_[1] = AL[r0 + 8][c * 8 + tig];
                al_[2] = AL[r0][c * 8 + tig + 4]; al_[3] = AL[r0 + 8][c * 8 + tig + 4];
                #pragma unroll
                for (int nf = 0; nf < 4; nf++) {
                    mma_bf16(acc[mf][nf], ah,  bh[nf]);
                    mma_bf16(acc[mf][nf], ah,  bl[nf]);
                    mma_bf16(acc[mf][nf], al_, bh[nf]);
                }
            }
        }
        __syncthreads();
    }
#undef LOAD_TILES

    // ---- epilogue: bias, store, per-graph column stats ----
    float s[4][2] = {}, q[4][2] = {};
    #pragma unroll
    for (int nf = 0; nf < 4; nf++) {
        int col = nbase + nbw + nf * 8 + 2 * tig;
        float2 bb = *(const float2*)&bias[col];
        #pragma unroll
        for (int mf = 0; mf < 4; mf++) {
            int r0 = mbase + mrw + mf * 16 + g;
            float v0 = acc[mf][nf][0] + bb.x, v1 = acc[mf][nf][1] + bb.y;
            float v2 = acc[mf][nf][2] + bb.x, v3 = acc[mf][nf][3] + bb.y;
            if (r0 < Mv) {
                float2 o = {v0, v1};
                *(float2*)&C[(long)r0 * DH + col] = o;
                s[nf][0] += v0; s[nf][1] += v1;
                q[nf][0] += v0 * v0; q[nf][1] += v1 * v1;
            }
            if (r0 + 8 < Mv) {
                float2 o = {v2, v3};
                *(float2*)&C[(long)(r0 + 8) * DH + col] = o;
                s[nf][0] += v2; s[nf][1] += v3;
                q[nf][0] += v2 * v2; q[nf][1] += v3 * v3;
            }
        }
    }
    if (stats) {
        float* st = stats + graph * 2 * DH;
        #pragma unroll
        for (int nf = 0; nf < 4; nf++)
            #pragma unroll
            for (int c2 = 0; c2 < 2; c2++) {
                float ss = s[nf][c2], qq = q[nf][c2];
                ss += __shfl_xor_sync(0xffffffffu, ss, 4);
                ss += __shfl_xor_sync(0xffffffffu, ss, 8);
                ss += __shfl_xor_sync(0xffffffffu, ss, 16);
                qq += __shfl_xor_sync(0xffffffffu, qq, 4);
                qq += __shfl_xor_sync(0xffffffffu, qq, 8);
                qq += __shfl_xor_sync(0xffffffffu, qq, 16);
                if (lane < 4) {
                    int col = nbase + nbw + nf * 8 + 2 * tig + c2;
                    atomicAdd(&st[col], ss);
                    atomicAdd(&st[DH + col], qq);
                }
            }
    }
}

// ---------------- BN finalize (both graphs in one launch) ----------------
__global__ void bn_finalize_k(const float* __restrict__ gamma, const float* __restrict__ beta,
                              float invNg, float invNq, float* stats,
                              float* scale, float* shift) {
    int t = threadIdx.x;             // 0..511
    int graph = t >> 8, c = t & 255;
    float invN = graph ? invNq : invNg;
    float* st = stats + graph * 2 * DH;
    float m  = st[c] * invN;
    float v  = st[DH + c] * invN - m * m;
    float sc = gamma[c] * rsqrtf(v + BNEPS);
    scale[graph * DH + c] = sc;
    shift[graph * DH + c] = fmaf(-m, sc, beta[c]);
    st[c] = 0.f; st[DH + c] = 0.f;
}

// ---------------- elementwise BN stages (split grid: g-blocks then q-blocks) ----------------
__global__ void bnrelu_stats_k(const float* __restrict__ X, float* __restrict__ Y,
                               const float* __restrict__ scale, const float* __restrict__ shift,
                               float* stats, int NG, int NGpad, int NTOT, int split) {
    int c = threadIdx.x, b = blockIdx.x;
    int graph, r0, r1;
    if (b < split) {
        graph = 0; int rpb = (NG + split - 1) / split;
        r0 = b * rpb; r1 = min(NG, r0 + rpb);
    } else {
        graph = 1; int nb = gridDim.x - split, bb = b - split;
        int nq = NTOT - NGpad; int rpb = (nq + nb - 1) / nb;
        r0 = NGpad + bb * rpb; r1 = min(NTOT, r0 + rpb);
    }
    float sc = scale[graph * DH + c], sh = shift[graph * DH + c];
    float s = 0.f, q = 0.f;
    for (int r = r0; r < r1; r++) {
        float v = fmaxf(fmaf(X[(long)r * DH + c], sc, sh), 0.f);
        Y[(long)r * DH + c] = v;
        s += v; q += v * v;
    }
    atomicAdd(&stats[graph * 2 * DH + c], s);
    atomicAdd(&stats[graph * 2 * DH + DH + c], q);
}

__global__ void bnrelu_resid_k(const float* __restrict__ X, float* __restrict__ H,
                               const float* __restrict__ scale, const float* __restrict__ shift,
                               int NG, int NGpad, int NTOT, int split) {
    int c = threadIdx.x, b = blockIdx.x;
    int graph, r0, r1;
    if (b < split) {
        graph = 0; int rpb = (NG + split - 1) / split;
        r0 = b * rpb; r1 = min(NG, r0 + rpb);
    } else {
        graph = 1; int nb = gridDim.x - split, bb = b - split;
        int nq = NTOT - NGpad; int rpb = (nq + nb - 1) / nb;
        r0 = NGpad + bb * rpb; r1 = min(NTOT, r0 + rpb);
    }
    float sc = scale[graph * DH + c], sh = shift[graph * DH + c];
    for (int r = r0; r < r1; r++) {
        long idx = (long)r * DH + c;
        H[idx] += fmaxf(fmaf(X[idx], sc, sh), 0.f);
    }
}

// ---------------- readout ----------------
__global__ void readout_k(const float* __restrict__ H, const int* __restrict__ gid,
                          float* __restrict__ out, int M) {
    int c  = threadIdx.x;
    int r0 = blockIdx.x * 64;
    if (r0 >= M) return;
    int r1 = min(M, r0 + 64);
    int cur = gid[r0];
    float acc = 0.f;
    for (int r = r0; r < r1; r++) {
        int g = gid[r];
        if (g != cur) { atomicAdd(&out[cur * DH + c], acc); acc = 0.f; cur = g; }
        acc += H[(long)r * DH + c];
    }
    atomicAdd(&out[cur * DH + c], acc);
}

// ---------------- final predictor ----------------
__global__ void predictor_k(const float* __restrict__ rd, const float* __restrict__ Wp1,
                            const float* __restrict__ bp1, const float* __restrict__ Wp2,
                            const float* __restrict__ bp2, float* __restrict__ out) {
    __shared__ float dvec[DH];
    __shared__ float hred[DH];
    int g = blockIdx.x, t = threadIdx.x;
    dvec[t] = fabsf(rd[g * DH + t] - rd[NGR * DH + g * DH + t]);
    __syncthreads();
    float acc = bp1[t];
    for (int k = 0; k < DH; k++) acc = fmaf(dvec[k], Wp1[k * DH + t], acc);
    hred[t] = fmaxf(acc, 0.f) * Wp2[t];
    __syncthreads();
    for (int s = DH / 2; s > 0; s >>= 1) {
        if (t < s) hred[t] += hred[t + s];
        __syncthreads();
    }
    if (t == 0) out[g] = hred[0] + bp2[0];
}

extern "C" void kernel_launch(void* const* d_in, const int* in_sizes, int n_in,
                              void* d_out, int out_size) {
    const float* X     = (const float*)d_in[0];
    const float* Xq    = (const float*)d_in[2];
    const float* W_emb = (const float*)d_in[4];
    const float* b_emb = (const float*)d_in[5];
    const float* eps   = (const float*)d_in[6];
    const float* W1    = (const float*)d_in[7];
    const float* b1    = (const float*)d_in[8];
    const float* bn1g  = (const float*)d_in[9];
    const float* bn1b  = (const float*)d_in[10];
    const float* W2    = (const float*)d_in[11];
    const float* b2    = (const float*)d_in[12];
    const float* bnAg  = (const float*)d_in[13];
    const float* bnAb  = (const float*)d_in[14];
    const float* bnGg  = (const float*)d_in[15];
    const float* bnGb  = (const float*)d_in[16];
    const float* Wp1   = (const float*)d_in[17];
    const float* bp1   = (const float*)d_in[18];
    const float* Wp2   = (const float*)d_in[19];
    const float* bp2   = (const float*)d_in[20];
    const int* src_g   = (const int*)d_in[21];
    const int* dst_g   = (const int*)d_in[22];
    const int* gid_g   = (const int*)d_in[23];
    const int* src_q   = (const int*)d_in[24];
    const int* dst_q   = (const int*)d_in[25];
    const int* gid_q   = (const int*)d_in[26];

    int NG_ = in_sizes[0] / 128;
    int NQ_ = in_sizes[2] / 128;
    int EG_ = in_sizes[21];
    int EQ_ = in_sizes[24];
    int NGpad = ((NG_ + 127) / 128) * 128;
    int NTOT  = NGpad + NQ_;
    int Etot  = EG_ + EQ_;

    float *Xc, *H, *T0, *T1, *stats, *scale, *shift, *rd;
    int *cnt, *wofs, *rowptr, *esrc;
    cudaGetSymbolAddress((void**)&Xc,     g_X);
    cudaGetSymbolAddress((void**)&H,      g_H);
    cudaGetSymbolAddress((void**)&T0,     g_T0);
    cudaGetSymbolAddress((void**)&T1,     g_T1);
    cudaGetSymbolAddress((void**)&stats,  g_stats);
    cudaGetSymbolAddress((void**)&scale,  g_scale);
    cudaGetSymbolAddress((void**)&shift,  g_shift);
    cudaGetSymbolAddress((void**)&rd,     g_read);
    cudaGetSymbolAddress((void**)&cnt,    g_cnt);
    cudaGetSymbolAddress((void**)&wofs,   g_wofs);
    cudaGetSymbolAddress((void**)&rowptr, g_rowptr);
    cudaGetSymbolAddress((void**)&esrc,   g_esrc);

    // combined node feature buffer (pad rows stay zero from static init)
    cudaMemcpyAsync(Xc, X, (size_t)NG_ * 128 * sizeof(float), cudaMemcpyDeviceToDevice);
    cudaMemcpyAsync(Xc + (long)NGpad * 128, Xq, (size_t)NQ_ * 128 * sizeof(float),
                    cudaMemcpyDeviceToDevice);

    // combined CSR (q nodes offset by NGpad)
    zeroi_kernel<<<(NTOT + 255) / 256, 256>>>(cnt, NTOT);
    hist_k<<<(EG_ + 255) / 256, 256>>>(dst_g, EG_, cnt, 0);
    hist_k<<<(EQ_ + 255) / 256, 256>>>(dst_q, EQ_, cnt, NGpad);
    scan_k<<<1, 1024>>>(cnt, rowptr, wofs, NTOT, Etot);
    fill_k<<<(EG_ + 255) / 256, 256>>>(src_g, dst_g, EG_, wofs, esrc, 0);
    fill_k<<<(EQ_ + 255) / 256, 256>>>(src_q, dst_q, EQ_, wofs, esrc, NGpad);

    zero_kernel<<<4, 256>>>(stats, 4 * DH);
    zero_kernel<<<(2 * NGR * DH + 255) / 256, 256>>>(rd, 2 * NGR * DH);

    float invNg = 1.f / (float)NG_, invNq = 1.f / (float)NQ_;
    dim3 gg((NTOT + 127) / 128, 2);
    const int SPLIT = 512, GRID_EW = 640;

    tgemm_k<128, false><<<gg, 256>>>(Xc, W_emb, b_emb, H, NG_, NGpad, NTOT,
                                     nullptr, nullptr, nullptr);
    for (int l = 0; l < NLAY; l++) {
        gather_k<<<(NTOT + 7) / 8, 256>>>(H, T0, rowptr, esrc, eps, l, NTOT);
        tgemm_k<256, false><<<gg, 256>>>(T0, W1 + l * DH * DH, b1 + l * DH, T1,
                                         NG_, NGpad, NTOT, nullptr, nullptr, stats);
        bn_finalize_k<<<1, 512>>>(bn1g + l * DH, bn1b + l * DH, invNg, invNq,
                                  stats, scale, shift);
        tgemm_k<256, true><<<gg, 256>>>(T1, W2 + l * DH * DH, b2 + l * DH, T0,
                                        NG_, NGpad, NTOT, scale, shift, stats);
        bn_finalize_k<<<1, 512>>>(bnAg + l * DH, bnAb + l * DH, invNg, invNq,
                                  stats, scale, shift);
        bnrelu_stats_k<<<GRID_EW, DH>>>(T0, T1, scale, shift, stats,
                                        NG_, NGpad, NTOT, SPLIT);
        bn_finalize_k<<<1, 512>>>(bnGg + l * DH, bnGb + l * DH, invNg, invNq,
                                  stats, scale, shift);
        bnrelu_resid_k<<<GRID_EW, DH>>>(T1, H, scale, shift,
                                        NG_, NGpad, NTOT, SPLIT);
    }
    readout_k<<<(NG_ + 63) / 64, 256>>>(H, gid_g, rd, NG_);
    readout_k<<<(NQ_ + 63) / 64, 256>>>(H + (long)NGpad * DH, gid_q, rd + NGR * DH, NQ_);

    predictor_k<<<NGR, DH>>>(rd, Wp1, bp1, Wp2, bp2, (float*)d_out);
}

// round 6
// speedup vs baseline: 1.4155x; 1.4155x over previous
#include <cuda_runtime.h>
#include <cuda_bf16.h>
#include <cstdint>

#define DH     256
#define NLAY   4
#define NGR    64
#define NTMAX  60160
#define EMAX   960000
#define BNEPS  1e-5f

// ---------------- scratch (static __device__ globals; no allocations) ----------------
__device__ float g_H [NTMAX*DH];
__device__ float g_T0[NTMAX*DH];
__device__ float g_T1[NTMAX*DH];
__device__ float g_stats[4*DH];     // [graph][sum/sumsq][DH]
__device__ float g_scale[2*DH];
__device__ float g_shift[2*DH];
__device__ float g_read[2*NGR*DH];
__device__ int   g_cnt [NTMAX];
__device__ int   g_wofs[NTMAX];
__device__ int   g_rowptr[NTMAX+1];
__device__ int   g_esrc[EMAX];
__device__ int   g_bsum[256];

// ---------------- small utility kernels ----------------
__global__ void zero_kernel(float* p, int n) {
    int i = blockIdx.x * blockDim.x + threadIdx.x;
    if (i < n) p[i] = 0.f;
}
__global__ void zeroi_kernel(int* p, int n) {
    int i = blockIdx.x * blockDim.x + threadIdx.x;
    if (i < n) p[i] = 0;
}

// ================= CSR build (by dst, combined over both graphs) =================
__global__ void hist_k(const int* __restrict__ dst, int E, int* __restrict__ cnt, int off) {
    int i = blockIdx.x * blockDim.x + threadIdx.x;
    if (i < E) atomicAdd(&cnt[dst[i] + off], 1);
}

// 3-phase parallel exclusive scan of cnt[0..N) -> rowptr/wofs
__global__ void blocksum_k(const int* __restrict__ cnt, int* __restrict__ bsum, int N) {
    __shared__ int sh[256];
    int i = blockIdx.x * 256 + threadIdx.x;
    sh[threadIdx.x] = (i < N) ? cnt[i] : 0;
    __syncthreads();
    for (int s = 128; s > 0; s >>= 1) {
        if (threadIdx.x < s) sh[threadIdx.x] += sh[threadIdx.x + s];
        __syncthreads();
    }
    if (threadIdx.x == 0) bsum[blockIdx.x] = sh[0];
}
__global__ void scanb_k(int* __restrict__ bsum, int nb) {
    __shared__ int sh[256];
    int t = threadIdx.x;
    sh[t] = (t < nb) ? bsum[t] : 0;
    __syncthreads();
    for (int off = 1; off < 256; off <<= 1) {
        int v = (t >= off) ? sh[t - off] : 0;
        __syncthreads();
        sh[t] += v;
        __syncthreads();
    }
    if (t < nb) bsum[t] = t ? sh[t - 1] : 0;   // exclusive
}
__global__ void scanfin_k(const int* __restrict__ cnt, const int* __restrict__ bpre,
                          int* __restrict__ rowptr, int* __restrict__ wofs, int N, int E) {
    __shared__ int sh[256];
    int i = blockIdx.x * 256 + threadIdx.x;
    int v = (i < N) ? cnt[i] : 0;
    sh[threadIdx.x] = v;
    __syncthreads();
    for (int off = 1; off < 256; off <<= 1) {
        int u = (threadIdx.x >= off) ? sh[threadIdx.x - off] : 0;
        __syncthreads();
        sh[threadIdx.x] += u;
        __syncthreads();
    }
    int excl = sh[threadIdx.x] - v + bpre[blockIdx.x];
    if (i < N) { rowptr[i] = excl; wofs[i] = excl; }
    if (blockIdx.x == 0 && threadIdx.x == 0) rowptr[N] = E;
}

__global__ void fill_k(const int* __restrict__ src, const int* __restrict__ dst, int E,
                       int* __restrict__ wofs, int* __restrict__ esrc, int off) {
    int i = blockIdx.x * blockDim.x + threadIdx.x;
    if (i < E) {
        int p = atomicAdd(&wofs[dst[i] + off], 1);
        esrc[p] = src[i] + off;
    }
}

// gather: T0[v] = (1+eps[l])*H[v] + sum_{e: dst=v} H[src[e]]   (one warp per node)
__global__ __launch_bounds__(256) void gather_k(
    const float* __restrict__ H, float* __restrict__ out,
    const int* __restrict__ rowptr, const int* __restrict__ esrc,
    const float* __restrict__ eps, int l, int N)
{
    int w    = (blockIdx.x * blockDim.x + threadIdx.x) >> 5;
    int lane = threadIdx.x & 31;
    if (w >= N) return;
    float e = 1.f + __ldg(&eps[l]);
    const float4* hr = (const float4*)(H + (long)w * DH);
    float4 a = hr[lane * 2], b = hr[lane * 2 + 1];
    a.x *= e; a.y *= e; a.z *= e; a.w *= e;
    b.x *= e; b.y *= e; b.z *= e; b.w *= e;
    int i0 = rowptr[w], i1 = rowptr[w + 1];
    for (int i = i0; i < i1; i++) {
        int s = __ldg(&esrc[i]);
        const float4* hs = (const float4*)(H + (long)s * DH);
        float4 u = hs[lane * 2], v = hs[lane * 2 + 1];
        a.x += u.x; a.y += u.y; a.z += u.z; a.w += u.w;
        b.x += v.x; b.y += v.y; b.z += v.z; b.w += v.w;
    }
    float4* o = (float4*)(out + (long)w * DH);
    o[lane * 2] = a; o[lane * 2 + 1] = b;
}

// ================= tensor-core GEMM (split-BF16 x3, ~fp32 accurate) =================
__device__ __forceinline__ uint32_t pack_hi(float e, float o, float& re, float& ro) {
    __nv_bfloat16 he = __float2bfloat16(e);
    __nv_bfloat16 ho = __float2bfloat16(o);
    re = e - __bfloat162float(he);
    ro = o - __bfloat162float(ho);
    return (uint32_t)__bfloat16_as_ushort(he) | ((uint32_t)__bfloat16_as_ushort(ho) << 16);
}
__device__ __forceinline__ uint32_t pack_lo(float re, float ro) {
    __nv_bfloat16 le = __float2bfloat16(re);
    __nv_bfloat16 lo = __float2bfloat16(ro);
    return (uint32_t)__bfloat16_as_ushort(le) | ((uint32_t)__bfloat16_as_ushort(lo) << 16);
}
__device__ __forceinline__ void mma_bf16(float* d, const uint32_t* a, const uint32_t* b) {
    asm volatile("mma.sync.aligned.m16n8k16.row.col.f32.bf16.bf16.f32 "
        "{%0,%1,%2,%3}, {%4,%5,%6,%7}, {%8,%9}, {%0,%1,%2,%3};\n"
        : "+f"(d[0]), "+f"(d[1]), "+f"(d[2]), "+f"(d[3])
        : "r"(a[0]), "r"(a[1]), "r"(a[2]), "r"(a[3]), "r"(b[0]), "r"(b[1]));
}

// C = op_A(A) @ W + bias.  Block tile 128x128, BK=32, 256 thr (8 warps, 64x32 each).
// Row space: [0,NG) = graph 0, [NGpad,NTOT) = graph 1; 128-row blocks never straddle.
template<int K, bool TRANS_A>
__global__ __launch_bounds__(256, 2) void tgemm_k(
    const float* __restrict__ A, const float* __restrict__ W,
    const float* __restrict__ bias, float* __restrict__ C,
    int NG, int NGpad, int NTOT,
    const float* __restrict__ scAll, const float* __restrict__ shAll,
    float* __restrict__ stats)
{
    __shared__ uint32_t AH[128][20];
    __shared__ uint32_t AL[128][20];
    __shared__ uint32_t BH[16][136];
    __shared__ uint32_t BL[16][136];
    __shared__ float sSc[256], sSh[256];

    const int tid  = threadIdx.x;
    const int wid  = tid >> 5, lane = tid & 31;
    const int g    = lane >> 2, tig = lane & 3;
    const int mrw  = (wid & 1) * 64;
    const int nbw  = (wid >> 1) * 32;
    const int mbase = blockIdx.x * 128;
    const int nbase = blockIdx.y * 128;
    const int graph = (mbase >= NGpad) ? 1 : 0;
    const int Mv    = graph ? NTOT : NG;

    if (TRANS_A) {
        sSc[tid] = scAll[graph * DH + tid];
        sSh[tid] = shAll[graph * DH + tid];
        __syncthreads();
    }

    float acc[4][4][4] = {};

    const int ar  = tid >> 1;          // A loader row 0..127
    const int akc = (tid & 1) * 16;    // A loader k base
    const int bkp = tid >> 4;          // B loader kpair 0..15
    const int bn0 = (tid & 15) * 8;    // B loader n base

    const int arow = mbase + ar;
    const bool av  = (arow < NG) || (arow >= NGpad && arow < NTOT);

    for (int kt = 0; kt < K; kt += 32) {
        // ---- stage A (optional fused BN+ReLU), split hi/lo ----
        #pragma unroll
        for (int j = 0; j < 4; j++) {
            int kc = akc + j * 4;
            float4 v = av ? *(const float4*)&A[(long)arow * K + kt + kc]
                          : make_float4(0.f, 0.f, 0.f, 0.f);
            float x0 = v.x, x1 = v.y, x2 = v.z, x3 = v.w;
            if (TRANS_A) {
                x0 = fmaxf(fmaf(x0, sSc[kt + kc    ], sSh[kt + kc    ]), 0.f);
                x1 = fmaxf(fmaf(x1, sSc[kt + kc + 1], sSh[kt + kc + 1]), 0.f);
                x2 = fmaxf(fmaf(x2, sSc[kt + kc + 2], sSh[kt + kc + 2]), 0.f);
                x3 = fmaxf(fmaf(x3, sSc[kt + kc + 3], sSh[kt + kc + 3]), 0.f);
            }
            float r0e, r0o, r1e, r1o;
            uint32_t h0 = pack_hi(x0, x1, r0e, r0o);
            uint32_t h1 = pack_hi(x2, x3, r1e, r1o);
            int kp = kc >> 1;
            AH[ar][kp] = h0;  AH[ar][kp + 1] = h1;
            AL[ar][kp] = pack_lo(r0e, r0o);
            AL[ar][kp + 1] = pack_lo(r1e, r1o);
        }
        // ---- stage B, split hi/lo ----
        {
            const float* We = &W[(long)(kt + 2 * bkp) * DH + nbase + bn0];
            const float* Wo = We + DH;
            #pragma unroll
            for (int j = 0; j < 2; j++) {
                float4 e4 = *(const float4*)(We + j * 4);
                float4 o4 = *(const float4*)(Wo + j * 4);
                float re, ro;
                uint4 h4, l4;
                h4.x = pack_hi(e4.x, o4.x, re, ro); l4.x = pack_lo(re, ro);
                h4.y = pack_hi(e4.y, o4.y, re, ro); l4.y = pack_lo(re, ro);
                h4.z = pack_hi(e4.z, o4.z, re, ro); l4.z = pack_lo(re, ro);
                h4.w = pack_hi(e4.w, o4.w, re, ro); l4.w = pack_lo(re, ro);
                *(uint4*)&BH[bkp][bn0 + j * 4] = h4;
                *(uint4*)&BL[bkp][bn0 + j * 4] = l4;
            }
        }
        __syncthreads();

        #pragma unroll
        for (int c = 0; c < 2; c++) {
            uint32_t bh[4][2], bl[4][2];
            #pragma unroll
            for (int nf = 0; nf < 4; nf++) {
                int cn = nbw + nf * 8 + g;
                bh[nf][0] = BH[c * 8 + tig][cn];
                bh[nf][1] = BH[c * 8 + tig + 4][cn];
                bl[nf][0] = BL[c * 8 + tig][cn];
                bl[nf][1] = BL[c * 8 + tig + 4][cn];
            }
            #pragma unroll
            for (int mf = 0; mf < 4; mf++) {
                int r0 = mrw + mf * 16 + g;
                uint32_t ah[4], al_[4];
                ah[0] = AH[r0][c * 8 + tig];      ah[1] = AH[r0 + 8][c * 8 + tig];
                ah[2] = AH[r0][c * 8 + tig + 4];  ah[3] = AH[r0 + 8][c * 8 + tig + 4];
                al_[0] = AL[r0][c * 8 + tig];     al_[1] = AL[r0 + 8][c * 8 + tig];
                al_[2] = AL[r0][c * 8 + tig + 4]; al_[3] = AL[r0 + 8][c * 8 + tig + 4];
                #pragma unroll
                for (int nf = 0; nf < 4; nf++) {
                    mma_bf16(acc[mf][nf], ah,  bh[nf]);
                    mma_bf16(acc[mf][nf], ah,  bl[nf]);
                    mma_bf16(acc[mf][nf], al_, bh[nf]);
                }
            }
        }
        __syncthreads();
    }

    // ---- epilogue: bias, store, per-graph column stats ----
    float s[4][2] = {}, q[4][2] = {};
    #pragma unroll
    for (int nf = 0; nf < 4; nf++) {
        int col = nbase + nbw + nf * 8 + 2 * tig;
        float2 bb = *(const float2*)&bias[col];
        #pragma unroll
        for (int mf = 0; mf < 4; mf++) {
            int r0 = mbase + mrw + mf * 16 + g;
            float v0 = acc[mf][nf][0] + bb.x, v1 = acc[mf][nf][1] + bb.y;
            float v2 = acc[mf][nf][2] + bb.x, v3 = acc[mf][nf][3] + bb.y;
            if (r0 < Mv) {
                float2 o = {v0, v1};
                *(float2*)&C[(long)r0 * DH + col] = o;
                s[nf][0] += v0; s[nf][1] += v1;
                q[nf][0] += v0 * v0; q[nf][1] += v1 * v1;
            }
            if (r0 + 8 < Mv) {
                float2 o = {v2, v3};
                *(float2*)&C[(long)(r0 + 8) * DH + col] = o;
                s[nf][0] += v2; s[nf][1] += v3;
                q[nf][0] += v2 * v2; q[nf][1] += v3 * v3;
            }
        }
    }
    if (stats) {
        float* st = stats + graph * 2 * DH;
        #pragma unroll
        for (int nf = 0; nf < 4; nf++)
            #pragma unroll
            for (int c2 = 0; c2 < 2; c2++) {
                float ss = s[nf][c2], qq = q[nf][c2];
                ss += __shfl_xor_sync(0xffffffffu, ss, 4);
                ss += __shfl_xor_sync(0xffffffffu, ss, 8);
                ss += __shfl_xor_sync(0xffffffffu, ss, 16);
                qq += __shfl_xor_sync(0xffffffffu, qq, 4);
                qq += __shfl_xor_sync(0xffffffffu, qq, 8);
                qq += __shfl_xor_sync(0xffffffffu, qq, 16);
                if (lane < 4) {
                    int col = nbase + nbw + nf * 8 + 2 * tig + c2;
                    atomicAdd(&st[col], ss);
                    atomicAdd(&st[DH + col], qq);
                }
            }
    }
}

// ---------------- BN finalize (both graphs in one launch) ----------------
__global__ void bn_finalize_k(const float* __restrict__ gamma, const float* __restrict__ beta,
                              float invNg, float invNq, float* stats,
                              float* scale, float* shift) {
    int t = threadIdx.x;             // 0..511
    int graph = t >> 8, c = t & 255;
    float invN = graph ? invNq : invNg;
    float* st = stats + graph * 2 * DH;
    float m  = st[c] * invN;
    float v  = st[DH + c] * invN - m * m;
    float sc = gamma[c] * rsqrtf(v + BNEPS);
    scale[graph * DH + c] = sc;
    shift[graph * DH + c] = fmaf(-m, sc, beta[c]);
    st[c] = 0.f; st[DH + c] = 0.f;
}

// ---------------- elementwise BN stages (split grid: g-blocks then q-blocks) ----------------
__global__ void bnrelu_stats_k(const float* __restrict__ X, float* __restrict__ Y,
                               const float* __restrict__ scale, const float* __restrict__ shift,
                               float* stats, int NG, int NGpad, int NTOT, int split) {
    int c = threadIdx.x, b = blockIdx.x;
    int graph, r0, r1;
    if (b < split) {
        graph = 0; int rpb = (NG + split - 1) / split;
        r0 = b * rpb; r1 = min(NG, r0 + rpb);
    } else {
        graph = 1; int nb = gridDim.x - split, bb = b - split;
        int nq = NTOT - NGpad; int rpb = (nq + nb - 1) / nb;
        r0 = NGpad + bb * rpb; r1 = min(NTOT, r0 + rpb);
    }
    float sc = scale[graph * DH + c], sh = shift[graph * DH + c];
    float s = 0.f, q = 0.f;
    for (int r = r0; r < r1; r++) {
        float v = fmaxf(fmaf(X[(long)r * DH + c], sc, sh), 0.f);
        Y[(long)r * DH + c] = v;
        s += v; q += v * v;
    }
    atomicAdd(&stats[graph * 2 * DH + c], s);
    atomicAdd(&stats[graph * 2 * DH + DH + c], q);
}

__global__ void bnrelu_resid_k(const float* __restrict__ X, float* __restrict__ H,
                               const float* __restrict__ scale, const float* __restrict__ shift,
                               int NG, int NGpad, int NTOT, int split) {
    int c = threadIdx.x, b = blockIdx.x;
    int graph, r0, r1;
    if (b < split) {
        graph = 0; int rpb = (NG + split - 1) / split;
        r0 = b * rpb; r1 = min(NG, r0 + rpb);
    } else {
        graph = 1; int nb = gridDim.x - split, bb = b - split;
        int nq = NTOT - NGpad; int rpb = (nq + nb - 1) / nb;
        r0 = NGpad + bb * rpb; r1 = min(NTOT, r0 + rpb);
    }
    float sc = scale[graph * DH + c], sh = shift[graph * DH + c];
    for (int r = r0; r < r1; r++) {
        long idx = (long)r * DH + c;
        H[idx] += fmaxf(fmaf(X[idx], sc, sh), 0.f);
    }
}

// ---------------- readout ----------------
__global__ void readout_k(const float* __restrict__ H, const int* __restrict__ gid,
                          float* __restrict__ out, int M) {
    int c  = threadIdx.x;
    int r0 = blockIdx.x * 64;
    if (r0 >= M) return;
    int r1 = min(M, r0 + 64);
    int cur = gid[r0];
    float acc = 0.f;
    for (int r = r0; r < r1; r++) {
        int g = gid[r];
        if (g != cur) { atomicAdd(&out[cur * DH + c], acc); acc = 0.f; cur = g; }
        acc += H[(long)r * DH + c];
    }
    atomicAdd(&out[cur * DH + c], acc);
}

// ---------------- final predictor ----------------
__global__ void predictor_k(const float* __restrict__ rd, const float* __restrict__ Wp1,
                            const float* __restrict__ bp1, const float* __restrict__ Wp2,
                            const float* __restrict__ bp2, float* __restrict__ out) {
    __shared__ float dvec[DH];
    __shared__ float hred[DH];
    int g = blockIdx.x, t = threadIdx.x;
    dvec[t] = fabsf(rd[g * DH + t] - rd[NGR * DH + g * DH + t]);
    __syncthreads();
    float acc = bp1[t];
    for (int k = 0; k < DH; k++) acc = fmaf(dvec[k], Wp1[k * DH + t], acc);
    hred[t] = fmaxf(acc, 0.f) * Wp2[t];
    __syncthreads();
    for (int s = DH / 2; s > 0; s >>= 1) {
        if (t < s) hred[t] += hred[t + s];
        __syncthreads();
    }
    if (t == 0) out[g] = hred[0] + bp2[0];
}

extern "C" void kernel_launch(void* const* d_in, const int* in_sizes, int n_in,
                              void* d_out, int out_size) {
    const float* X     = (const float*)d_in[0];
    const float* Xq    = (const float*)d_in[2];
    const float* W_emb = (const float*)d_in[4];
    const float* b_emb = (const float*)d_in[5];
    const float* eps   = (const float*)d_in[6];
    const float* W1    = (const float*)d_in[7];
    const float* b1    = (const float*)d_in[8];
    const float* bn1g  = (const float*)d_in[9];
    const float* bn1b  = (const float*)d_in[10];
    const float* W2    = (const float*)d_in[11];
    const float* b2    = (const float*)d_in[12];
    const float* bnAg  = (const float*)d_in[13];
    const float* bnAb  = (const float*)d_in[14];
    const float* bnGg  = (const float*)d_in[15];
    const float* bnGb  = (const float*)d_in[16];
    const float* Wp1   = (const float*)d_in[17];
    const float* bp1   = (const float*)d_in[18];
    const float* Wp2   = (const float*)d_in[19];
    const float* bp2   = (const float*)d_in[20];
    const int* src_g   = (const int*)d_in[21];
    const int* dst_g   = (const int*)d_in[22];
    const int* gid_g   = (const int*)d_in[23];
    const int* src_q   = (const int*)d_in[24];
    const int* dst_q   = (const int*)d_in[25];
    const int* gid_q   = (const int*)d_in[26];

    int NG_ = in_sizes[0] / 128;
    int NQ_ = in_sizes[2] / 128;
    int EG_ = in_sizes[21];
    int EQ_ = in_sizes[24];
    int NGpad = ((NG_ + 127) / 128) * 128;
    int NTOT  = NGpad + NQ_;
    int Etot  = EG_ + EQ_;

    float *H, *T0, *T1, *stats, *scale, *shift, *rd;
    int *cnt, *wofs, *rowptr, *esrc, *bsum;
    cudaGetSymbolAddress((void**)&H,      g_H);
    cudaGetSymbolAddress((void**)&T0,     g_T0);
    cudaGetSymbolAddress((void**)&T1,     g_T1);
    cudaGetSymbolAddress((void**)&stats,  g_stats);
    cudaGetSymbolAddress((void**)&scale,  g_scale);
    cudaGetSymbolAddress((void**)&shift,  g_shift);
    cudaGetSymbolAddress((void**)&rd,     g_read);
    cudaGetSymbolAddress((void**)&cnt,    g_cnt);
    cudaGetSymbolAddress((void**)&wofs,   g_wofs);
    cudaGetSymbolAddress((void**)&rowptr, g_rowptr);
    cudaGetSymbolAddress((void**)&esrc,   g_esrc);
    cudaGetSymbolAddress((void**)&bsum,   g_bsum);

    // combined CSR (q nodes offset by NGpad); pad nodes have zero degree
    int nb = (NTOT + 255) / 256;
    zeroi_kernel<<<nb, 256>>>(cnt, NTOT);
    hist_k<<<(EG_ + 255) / 256, 256>>>(dst_g, EG_, cnt, 0);
    hist_k<<<(EQ_ + 255) / 256, 256>>>(dst_q, EQ_, cnt, NGpad);
    blocksum_k<<<nb, 256>>>(cnt, bsum, NTOT);
    scanb_k<<<1, 256>>>(bsum, nb);
    scanfin_k<<<nb, 256>>>(cnt, bsum, rowptr, wofs, NTOT, Etot);
    fill_k<<<(EG_ + 255) / 256, 256>>>(src_g, dst_g, EG_, wofs, esrc, 0);
    fill_k<<<(EQ_ + 255) / 256, 256>>>(src_q, dst_q, EQ_, wofs, esrc, NGpad);

    zero_kernel<<<4, 256>>>(stats, 4 * DH);
    zero_kernel<<<(2 * NGR * DH + 255) / 256, 256>>>(rd, 2 * NGR * DH);

    float invNg = 1.f / (float)NG_, invNq = 1.f / (float)NQ_;
    dim3 gg((NTOT + 127) / 128, 2);
    const int SPLIT = 512, GRID_EW = 640;

    // embedding GEMMs straight from the inputs (no copy); pad rows of H never read
    dim3 gge(NGpad / 128, 2), ggq((NQ_ + 127) / 128, 2);
    tgemm_k<128, false><<<gge, 256>>>(X, W_emb, b_emb, H, NG_, 1 << 30, NG_,
                                      nullptr, nullptr, nullptr);
    tgemm_k<128, false><<<ggq, 256>>>(Xq, W_emb, b_emb, H + (long)NGpad * DH,
                                      NQ_, 1 << 30, NQ_, nullptr, nullptr, nullptr);

    for (int l = 0; l < NLAY; l++) {
        gather_k<<<(NTOT + 7) / 8, 256>>>(H, T0, rowptr, esrc, eps, l, NTOT);
        tgemm_k<256, false><<<gg, 256>>>(T0, W1 + l * DH * DH, b1 + l * DH, T1,
                                         NG_, NGpad, NTOT, nullptr, nullptr, stats);
        bn_finalize_k<<<1, 512>>>(bn1g + l * DH, bn1b + l * DH, invNg, invNq,
                                  stats, scale, shift);
        tgemm_k<256, true><<<gg, 256>>>(T1, W2 + l * DH * DH, b2 + l * DH, T0,
                                        NG_, NGpad, NTOT, scale, shift, stats);
        bn_finalize_k<<<1, 512>>>(bnAg + l * DH, bnAb + l * DH, invNg, invNq,
                                  stats, scale, shift);
        bnrelu_stats_k<<<GRID_EW, DH>>>(T0, T1, scale, shift, stats,
                                        NG_, NGpad, NTOT, SPLIT);
        bn_finalize_k<<<1, 512>>>(bnGg + l * DH, bnGb + l * DH, invNg, invNq,
                                  stats, scale, shift);
        bnrelu_resid_k<<<GRID_EW, DH>>>(T1, H, scale, shift,
                                        NG_, NGpad, NTOT, SPLIT);
    }
    readout_k<<<(NG_ + 63) / 64, 256>>>(H, gid_g, rd, NG_);
    readout_k<<<(NQ_ + 63) / 64, 256>>>(H + (long)NGpad * DH, gid_q, rd + NGR * DH, NQ_);

    predictor_k<<<NGR, DH>>>(rd, Wp1, bp1, Wp2, bp2, (float*)d_out);
}

// round 10
// speedup vs baseline: 1.4818x; 1.0468x over previous
#include <cuda_runtime.h>
#include <cuda_bf16.h>
#include <cstdint>

#define DH     256
#define NLAY   4
#define NGR    64
#define NTMAX  60160
#define EMAX   960000
#define BNEPS  1e-5f

// ---------------- scratch (static __device__ globals; no allocations) ----------------
__device__ float g_H [NTMAX*DH];
__device__ float g_T0[NTMAX*DH];
__device__ float g_T1[NTMAX*DH];
__device__ float g_stats[NLAY*3*1024];   // [layer][stage: bn1,bnA,bnG][graph*512 + {c | 256+c}]
__device__ float g_read[2*NGR*DH];
__device__ int   g_cnt [NTMAX];
__device__ int   g_wofs[NTMAX];
__device__ int   g_rowptr[NTMAX+1];
__device__ int   g_esrc[EMAX];
__device__ int   g_bsum[256];

// ---------------- small utility kernels ----------------
__global__ void zero_kernel(float* p, int n) {
    int i = blockIdx.x * blockDim.x + threadIdx.x;
    if (i < n) p[i] = 0.f;
}
__global__ void zeroi_kernel(int* p, int n) {
    int i = blockIdx.x * blockDim.x + threadIdx.x;
    if (i < n) p[i] = 0;
}

// ---------------- inline BN scale/shift from raw stats ----------------
__device__ __forceinline__ void bn_coeff(const float* st, const float* gamma,
                                         const float* beta, float invN, int c,
                                         float& sc, float& sh) {
    float m = st[c] * invN;
    float v = st[256 + c] * invN - m * m;
    sc = gamma[c] * rsqrtf(v + BNEPS);
    sh = fmaf(-m, sc, beta[c]);
}

// ================= CSR build (by dst, combined over both graphs) =================
__global__ void hist_k(const int* __restrict__ dst, int E, int* __restrict__ cnt, int off) {
    int i = blockIdx.x * blockDim.x + threadIdx.x;
    if (i < E) atomicAdd(&cnt[dst[i] + off], 1);
}

__global__ void blocksum_k(const int* __restrict__ cnt, int* __restrict__ bsum, int N) {
    __shared__ int sh[256];
    int i = blockIdx.x * 256 + threadIdx.x;
    sh[threadIdx.x] = (i < N) ? cnt[i] : 0;
    __syncthreads();
    for (int s = 128; s > 0; s >>= 1) {
        if (threadIdx.x < s) sh[threadIdx.x] += sh[threadIdx.x + s];
        __syncthreads();
    }
    if (threadIdx.x == 0) bsum[blockIdx.x] = sh[0];
}
__global__ void scanb_k(int* __restrict__ bsum, int nb) {
    __shared__ int sh[256];
    int t = threadIdx.x;
    sh[t] = (t < nb) ? bsum[t] : 0;
    __syncthreads();
    for (int off = 1; off < 256; off <<= 1) {
        int v = (t >= off) ? sh[t - off] : 0;
        __syncthreads();
        sh[t] += v;
        __syncthreads();
    }
    if (t < nb) bsum[t] = t ? sh[t - 1] : 0;
}
__global__ void scanfin_k(const int* __restrict__ cnt, const int* __restrict__ bpre,
                          int* __restrict__ rowptr, int* __restrict__ wofs, int N, int E) {
    __shared__ int sh[256];
    int i = blockIdx.x * 256 + threadIdx.x;
    int v = (i < N) ? cnt[i] : 0;
    sh[threadIdx.x] = v;
    __syncthreads();
    for (int off = 1; off < 256; off <<= 1) {
        int u = (threadIdx.x >= off) ? sh[threadIdx.x - off] : 0;
        __syncthreads();
        sh[threadIdx.x] += u;
        __syncthreads();
    }
    int excl = sh[threadIdx.x] - v + bpre[blockIdx.x];
    if (i < N) { rowptr[i] = excl; wofs[i] = excl; }
    if (blockIdx.x == 0 && threadIdx.x == 0) rowptr[N] = E;
}

__global__ void fill_k(const int* __restrict__ src, const int* __restrict__ dst, int E,
                       int* __restrict__ wofs, int* __restrict__ esrc, int off) {
    int i = blockIdx.x * blockDim.x + threadIdx.x;
    if (i < E) {
        int p = atomicAdd(&wofs[dst[i] + off], 1);
        esrc[p] = src[i] + off;
    }
}

// gather: T0[v] = (1+eps[l])*H[v] + sum_{e: dst=v} H[src[e]]   (one warp per node)
__global__ __launch_bounds__(256) void gather_k(
    const float* __restrict__ H, float* __restrict__ out,
    const int* __restrict__ rowptr, const int* __restrict__ esrc,
    const float* __restrict__ eps, int l, int N)
{
    int w    = (blockIdx.x * blockDim.x + threadIdx.x) >> 5;
    int lane = threadIdx.x & 31;
    if (w >= N) return;
    float e = 1.f + __ldg(&eps[l]);
    const float4* hr = (const float4*)(H + (long)w * DH);
    float4 a = hr[lane * 2], b = hr[lane * 2 + 1];
    a.x *= e; a.y *= e; a.z *= e; a.w *= e;
    b.x *= e; b.y *= e; b.z *= e; b.w *= e;
    int i0 = rowptr[w], i1 = rowptr[w + 1];
    for (int i = i0; i < i1; i++) {
        int s = __ldg(&esrc[i]);
        const float4* hs = (const float4*)(H + (long)s * DH);
        float4 u = hs[lane * 2], v = hs[lane * 2 + 1];
        a.x += u.x; a.y += u.y; a.z += u.z; a.w += u.w;
        b.x += v.x; b.y += v.y; b.z += v.z; b.w += v.w;
    }
    float4* o = (float4*)(out + (long)w * DH);
    o[lane * 2] = a; o[lane * 2 + 1] = b;
}

// ================= tensor-core GEMM (split-BF16 x3, ~fp32 accurate) =================
__device__ __forceinline__ uint32_t pack_hi(float e, float o, float& re, float& ro) {
    __nv_bfloat16 he = __float2bfloat16(e);
    __nv_bfloat16 ho = __float2bfloat16(o);
    re = e - __bfloat162float(he);
    ro = o - __bfloat162float(ho);
    return (uint32_t)__bfloat16_as_ushort(he) | ((uint32_t)__bfloat16_as_ushort(ho) << 16);
}
__device__ __forceinline__ uint32_t pack_lo(float re, float ro) {
    __nv_bfloat16 le = __float2bfloat16(re);
    __nv_bfloat16 lo = __float2bfloat16(ro);
    return (uint32_t)__bfloat16_as_ushort(le) | ((uint32_t)__bfloat16_as_ushort(lo) << 16);
}
__device__ __forceinline__ void mma_bf16(float* d, const uint32_t* a, const uint32_t* b) {
    asm volatile("mma.sync.aligned.m16n8k16.row.col.f32.bf16.bf16.f32 "
        "{%0,%1,%2,%3}, {%4,%5,%6,%7}, {%8,%9}, {%0,%1,%2,%3};\n"
        : "+f"(d[0]), "+f"(d[1]), "+f"(d[2]), "+f"(d[3])
        : "r"(a[0]), "r"(a[1]), "r"(a[2]), "r"(a[3]), "r"(b[0]), "r"(b[1]));
}

// C = op_A(A) @ W + bias.  Block tile 128x128, BK=32, 256 thr (8 warps, 64x32 each).
// Row space: [0,NG) = graph 0, [NGpad,NTOT) = graph 1; 128-row blocks never straddle.
// TRANS_A: A is transformed by relu(bn(.)) whose scale/shift are computed inline
// from raw stats (stin) + gamma/beta. stout: per-graph column stats of C.
template<int K, bool TRANS_A>
__global__ __launch_bounds__(256, 2) void tgemm_k(
    const float* __restrict__ A, const float* __restrict__ W,
    const float* __restrict__ bias, float* __restrict__ C,
    int NG, int NGpad, int NTOT,
    const float* __restrict__ stin, const float* __restrict__ gamma,
    const float* __restrict__ beta, float invNg, float invNq,
    float* __restrict__ stout)
{
    __shared__ uint32_t AH[128][20];
    __shared__ uint32_t AL[128][20];
    __shared__ uint32_t BH[16][136];
    __shared__ uint32_t BL[16][136];
    __shared__ float sSc[256], sSh[256];

    const int tid  = threadIdx.x;
    const int wid  = tid >> 5, lane = tid & 31;
    const int g    = lane >> 2, tig = lane & 3;
    const int mrw  = (wid & 1) * 64;
    const int nbw  = (wid >> 1) * 32;
    const int mbase = blockIdx.x * 128;
    const int nbase = blockIdx.y * 128;
    const int graph = (mbase >= NGpad) ? 1 : 0;
    const int Mv    = graph ? NTOT : NG;

    if (TRANS_A) {
        float sc, sh;
        bn_coeff(stin + graph * 512, gamma, beta, graph ? invNq : invNg, tid, sc, sh);
        sSc[tid] = sc; sSh[tid] = sh;
        __syncthreads();
    }

    float acc[4][4][4] = {};

    const int ar  = tid >> 1;
    const int akc = (tid & 1) * 16;
    const int bkp = tid >> 4;
    const int bn0 = (tid & 15) * 8;

    const int arow = mbase + ar;
    const bool av  = (arow < NG) || (arow >= NGpad && arow < NTOT);

    for (int kt = 0; kt < K; kt += 32) {
        #pragma unroll
        for (int j = 0; j < 4; j++) {
            int kc = akc + j * 4;
            float4 v = av ? *(const float4*)&A[(long)arow * K + kt + kc]
                          : make_float4(0.f, 0.f, 0.f, 0.f);
            float x0 = v.x, x1 = v.y, x2 = v.z, x3 = v.w;
            if (TRANS_A) {
                x0 = fmaxf(fmaf(x0, sSc[kt + kc    ], sSh[kt + kc    ]), 0.f);
                x1 = fmaxf(fmaf(x1, sSc[kt + kc + 1], sSh[kt + kc + 1]), 0.f);
                x2 = fmaxf(fmaf(x2, sSc[kt + kc + 2], sSh[kt + kc + 2]), 0.f);
                x3 = fmaxf(fmaf(x3, sSc[kt + kc + 3], sSh[kt + kc + 3]), 0.f);
            }
            float r0e, r0o, r1e, r1o;
            uint32_t h0 = pack_hi(x0, x1, r0e, r0o);
            uint32_t h1 = pack_hi(x2, x3, r1e, r1o);
            int kp = kc >> 1;
            AH[ar][kp] = h0;  AH[ar][kp + 1] = h1;
            AL[ar][kp] = pack_lo(r0e, r0o);
            AL[ar][kp + 1] = pack_lo(r1e, r1o);
        }
        {
            const float* We = &W[(long)(kt + 2 * bkp) * DH + nbase + bn0];
            const float* Wo = We + DH;
            #pragma unroll
            for (int j = 0; j < 2; j++) {
                float4 e4 = *(const float4*)(We + j * 4);
                float4 o4 = *(const float4*)(Wo + j * 4);
                float re, ro;
                uint4 h4, l4;
                h4.x = pack_hi(e4.x, o4.x, re, ro); l4.x = pack_lo(re, ro);
                h4.y = pack_hi(e4.y, o4.y, re, ro); l4.y = pack_lo(re, ro);
                h4.z = pack_hi(e4.z, o4.z, re, ro); l4.z = pack_lo(re, ro);
                h4.w = pack_hi(e4.w, o4.w, re, ro); l4.w = pack_lo(re, ro);
                *(uint4*)&BH[bkp][bn0 + j * 4] = h4;
                *(uint4*)&BL[bkp][bn0 + j * 4] = l4;
            }
        }
        __syncthreads();

        #pragma unroll
        for (int c = 0; c < 2; c++) {
            uint32_t bh[4][2], bl[4][2];
            #pragma unroll
            for (int nf = 0; nf < 4; nf++) {
                int cn = nbw + nf * 8 + g;
                bh[nf][0] = BH[c * 8 + tig][cn];
                bh[nf][1] = BH[c * 8 + tig + 4][cn];
                bl[nf][0] = BL[c * 8 + tig][cn];
                bl[nf][1] = BL[c * 8 + tig + 4][cn];
            }
            #pragma unroll
            for (int mf = 0; mf < 4; mf++) {
                int r0 = mrw + mf * 16 + g;
                uint32_t ah[4], al_[4];
                ah[0] = AH[r0][c * 8 + tig];      ah[1] = AH[r0 + 8][c * 8 + tig];
                ah[2] = AH[r0][c * 8 + tig + 4];  ah[3] = AH[r0 + 8][c * 8 + tig + 4];
                al_[0] = AL[r0][c * 8 + tig];     al_[1] = AL[r0 + 8][c * 8 + tig];
                al_[2] = AL[r0][c * 8 + tig + 4]; al_[3] = AL[r0 + 8][c * 8 + tig + 4];
                #pragma unroll
                for (int nf = 0; nf < 4; nf++) {
                    mma_bf16(acc[mf][nf], ah,  bh[nf]);
                    mma_bf16(acc[mf][nf], ah,  bl[nf]);
                    mma_bf16(acc[mf][nf], al_, bh[nf]);
                }
            }
        }
        __syncthreads();
    }

    // ---- epilogue: bias, store, per-graph column stats ----
    float s[4][2] = {}, q[4][2] = {};
    #pragma unroll
    for (int nf = 0; nf < 4; nf++) {
        int col = nbase + nbw + nf * 8 + 2 * tig;
        float2 bb = *(const float2*)&bias[col];
        #pragma unroll
        for (int mf = 0; mf < 4; mf++) {
            int r0 = mbase + mrw + mf * 16 + g;
            float v0 = acc[mf][nf][0] + bb.x, v1 = acc[mf][nf][1] + bb.y;
            float v2 = acc[mf][nf][2] + bb.x, v3 = acc[mf][nf][3] + bb.y;
            if (r0 < Mv) {
                float2 o = {v0, v1};
                *(float2*)&C[(long)r0 * DH + col] = o;
                s[nf][0] += v0; s[nf][1] += v1;
                q[nf][0] += v0 * v0; q[nf][1] += v1 * v1;
            }
            if (r0 + 8 < Mv) {
                float2 o = {v2, v3};
                *(float2*)&C[(long)(r0 + 8) * DH + col] = o;
                s[nf][0] += v2; s[nf][1] += v3;
                q[nf][0] += v2 * v2; q[nf][1] += v3 * v3;
            }
        }
    }
    if (stout) {
        float* st = stout + graph * 512;
        #pragma unroll
        for (int nf = 0; nf < 4; nf++)
            #pragma unroll
            for (int c2 = 0; c2 < 2; c2++) {
                float ss = s[nf][c2], qq = q[nf][c2];
                ss += __shfl_xor_sync(0xffffffffu, ss, 4);
                ss += __shfl_xor_sync(0xffffffffu, ss, 8);
                ss += __shfl_xor_sync(0xffffffffu, ss, 16);
                qq += __shfl_xor_sync(0xffffffffu, qq, 4);
                qq += __shfl_xor_sync(0xffffffffu, qq, 8);
                qq += __shfl_xor_sync(0xffffffffu, qq, 16);
                if (lane < 4) {
                    int col = nbase + nbw + nf * 8 + 2 * tig + c2;
                    atomicAdd(&st[col], ss);
                    atomicAdd(&st[256 + col], qq);
                }
            }
    }
}

// ---------------- elementwise stage 1: stats of relu(bnA(T0)) -> bnG stats ----------------
__global__ void bnstats_k(const float* __restrict__ T0,
                          const float* __restrict__ stA, const float* __restrict__ gA,
                          const float* __restrict__ bA, float* __restrict__ stG,
                          float invNg, float invNq,
                          int NG, int NGpad, int NTOT, int split) {
    int c = threadIdx.x, b = blockIdx.x;
    int graph, r0, r1;
    if (b < split) {
        graph = 0; int rpb = (NG + split - 1) / split;
        r0 = b * rpb; r1 = min(NG, r0 + rpb);
    } else {
        graph = 1; int nb = gridDim.x - split, bb = b - split;
        int nq = NTOT - NGpad; int rpb = (nq + nb - 1) / nb;
        r0 = NGpad + bb * rpb; r1 = min(NTOT, r0 + rpb);
    }
    float scA, shA;
    bn_coeff(stA + graph * 512, gA, bA, graph ? invNq : invNg, c, scA, shA);
    float s = 0.f, q = 0.f;
    for (int r = r0; r < r1; r++) {
        float v = fmaxf(fmaf(T0[(long)r * DH + c], scA, shA), 0.f);
        s += v; q += v * v;
    }
    atomicAdd(&stG[graph * 512 + c], s);
    atomicAdd(&stG[graph * 512 + 256 + c], q);
}

// ---------------- elementwise stage 2: H += relu(bnG(relu(bnA(T0)))) ----------------
__global__ void bnresid_k(const float* __restrict__ T0, float* __restrict__ H,
                          const float* __restrict__ stA, const float* __restrict__ gA,
                          const float* __restrict__ bA,
                          const float* __restrict__ stG, const float* __restrict__ gG,
                          const float* __restrict__ bG,
                          float invNg, float invNq,
                          int NG, int NGpad, int NTOT, int split) {
    int c = threadIdx.x, b = blockIdx.x;
    int graph, r0, r1;
    if (b < split) {
        graph = 0; int rpb = (NG + split - 1) / split;
        r0 = b * rpb; r1 = min(NG, r0 + rpb);
    } else {
        graph = 1; int nb = gridDim.x - split, bb = b - split;
        int nq = NTOT - NGpad; int rpb = (nq + nb - 1) / nb;
        r0 = NGpad + bb * rpb; r1 = min(NTOT, r0 + rpb);
    }
    float invN = graph ? invNq : invNg;
    float scA, shA, scG, shG;
    bn_coeff(stA + graph * 512, gA, bA, invN, c, scA, shA);
    bn_coeff(stG + graph * 512, gG, bG, invN, c, scG, shG);
    for (int r = r0; r < r1; r++) {
        long idx = (long)r * DH + c;
        float v = fmaxf(fmaf(T0[idx], scA, shA), 0.f);
        H[idx] += fmaxf(fmaf(v, scG, shG), 0.f);
    }
}

// ---------------- merged readout for both graphs ----------------
__global__ void readout_k(const float* __restrict__ H,
                          const int* __restrict__ gidg, const int* __restrict__ gidq,
                          float* __restrict__ rd, int NG, int NGpad, int NQ, int nbG) {
    int c = threadIdx.x, b = blockIdx.x;
    const float* Hp; const int* gid; float* out; int r0, M;
    if (b < nbG) { Hp = H; gid = gidg; out = rd; r0 = b * 64; M = NG; }
    else { Hp = H + (long)NGpad * DH; gid = gidq; out = rd + NGR * DH;
           r0 = (b - nbG) * 64; M = NQ; }
    if (r0 >= M) return;
    int r1 = min(M, r0 + 64);
    int cur = gid[r0];
    float acc = 0.f;
    for (int r = r0; r < r1; r++) {
        int g = gid[r];
        if (g != cur) { atomicAdd(&out[cur * DH + c], acc); acc = 0.f; cur = g; }
        acc += Hp[(long)r * DH + c];
    }
    atomicAdd(&out[cur * DH + c], acc);
}

// ---------------- final predictor ----------------
__global__ void predictor_k(const float* __restrict__ rd, const float* __restrict__ Wp1,
                            const float* __restrict__ bp1, const float* __restrict__ Wp2,
                            const float* __restrict__ bp2, float* __restrict__ out) {
    __shared__ float dvec[DH];
    __shared__ float hred[DH];
    int g = blockIdx.x, t = threadIdx.x;
    dvec[t] = fabsf(rd[g * DH + t] - rd[NGR * DH + g * DH + t]);
    __syncthreads();
    float acc = bp1[t];
    for (int k = 0; k < DH; k++) acc = fmaf(dvec[k], Wp1[k * DH + t], acc);
    hred[t] = fmaxf(acc, 0.f) * Wp2[t];
    __syncthreads();
    for (int s = DH / 2; s > 0; s >>= 1) {
        if (t < s) hred[t] += hred[t + s];
        __syncthreads();
    }
    if (t == 0) out[g] = hred[0] + bp2[0];
}

extern "C" void kernel_launch(void* const* d_in, const int* in_sizes, int n_in,
                              void* d_out, int out_size) {
    const float* X     = (const float*)d_in[0];
    const float* Xq    = (const float*)d_in[2];
    const float* W_emb = (const float*)d_in[4];
    const float* b_emb = (const float*)d_in[5];
    const float* eps   = (const float*)d_in[6];
    const float* W1    = (const float*)d_in[7];
    const float* b1    = (const float*)d_in[8];
    const float* bn1g  = (const float*)d_in[9];
    const float* bn1b  = (const float*)d_in[10];
    const float* W2    = (const float*)d_in[11];
    const float* b2    = (const float*)d_in[12];
    const float* bnAg  = (const float*)d_in[13];
    const float* bnAb  = (const float*)d_in[14];
    const float* bnGg  = (const float*)d_in[15];
    const float* bnGb  = (const float*)d_in[16];
    const float* Wp1   = (const float*)d_in[17];
    const float* bp1   = (const float*)d_in[18];
    const float* Wp2   = (const float*)d_in[19];
    const float* bp2   = (const float*)d_in[20];
    const int* src_g   = (const int*)d_in[21];
    const int* dst_g   = (const int*)d_in[22];
    const int* gid_g   = (const int*)d_in[23];
    const int* src_q   = (const int*)d_in[24];
    const int* dst_q   = (const int*)d_in[25];
    const int* gid_q   = (const int*)d_in[26];

    int NG_ = in_sizes[0] / 128;
    int NQ_ = in_sizes[2] / 128;
    int EG_ = in_sizes[21];
    int EQ_ = in_sizes[24];
    int NGpad = ((NG_ + 127) / 128) * 128;
    int NTOT  = NGpad + NQ_;
    int Etot  = EG_ + EQ_;

    float *H, *T0, *T1, *stats, *rd;
    int *cnt, *wofs, *rowptr, *esrc, *bsum;
    cudaGetSymbolAddress((void**)&H,      g_H);
    cudaGetSymbolAddress((void**)&T0,     g_T0);
    cudaGetSymbolAddress((void**)&T1,     g_T1);
    cudaGetSymbolAddress((void**)&stats,  g_stats);
    cudaGetSymbolAddress((void**)&rd,     g_read);
    cudaGetSymbolAddress((void**)&cnt,    g_cnt);
    cudaGetSymbolAddress((void**)&wofs,   g_wofs);
    cudaGetSymbolAddress((void**)&rowptr, g_rowptr);
    cudaGetSymbolAddress((void**)&esrc,   g_esrc);
    cudaGetSymbolAddress((void**)&bsum,   g_bsum);

    // combined CSR (q nodes offset by NGpad); pad nodes have zero degree
    int nb = (NTOT + 255) / 256;
    zeroi_kernel<<<nb, 256>>>(cnt, NTOT);
    hist_k<<<(EG_ + 255) / 256, 256>>>(dst_g, EG_, cnt, 0);
    hist_k<<<(EQ_ + 255) / 256, 256>>>(dst_q, EQ_, cnt, NGpad);
    blocksum_k<<<nb, 256>>>(cnt, bsum, NTOT);
    scanb_k<<<1, 256>>>(bsum, nb);
    scanfin_k<<<nb, 256>>>(cnt, bsum, rowptr, wofs, NTOT, Etot);
    fill_k<<<(EG_ + 255) / 256, 256>>>(src_g, dst_g, EG_, wofs, esrc, 0);
    fill_k<<<(EQ_ + 255) / 256, 256>>>(src_q, dst_q, EQ_, wofs, esrc, NGpad);

    zero_kernel<<<(NLAY * 3 * 1024 + 255) / 256, 256>>>(stats, NLAY * 3 * 1024);
    zero_kernel<<<(2 * NGR * DH + 255) / 256, 256>>>(rd, 2 * NGR * DH);

    float invNg = 1.f / (float)NG_, invNq = 1.f / (float)NQ_;
    dim3 gg((NTOT + 127) / 128, 2);
    const int SPLIT = 512, GRID_EW = 640;

    // embedding GEMMs straight from the inputs (no copy); pad rows of H never read
    dim3 gge(NGpad / 128, 2), ggq((NQ_ + 127) / 128, 2);
    tgemm_k<128, false><<<gge, 256>>>(X, W_emb, b_emb, H, NG_, 1 << 30, NG_,
                                      nullptr, nullptr, nullptr, 1.f, 1.f, nullptr);
    tgemm_k<128, false><<<ggq, 256>>>(Xq, W_emb, b_emb, H + (long)NGpad * DH,
                                      NQ_, 1 << 30, NQ_,
                                      nullptr, nullptr, nullptr, 1.f, 1.f, nullptr);

    for (int l = 0; l < NLAY; l++) {
        float* st1 = stats + (l * 3 + 0) * 1024;
        float* stA = stats + (l * 3 + 1) * 1024;
        float* stG = stats + (l * 3 + 2) * 1024;
        gather_k<<<(NTOT + 7) / 8, 256>>>(H, T0, rowptr, esrc, eps, l, NTOT);
        tgemm_k<256, false><<<gg, 256>>>(T0, W1 + l * DH * DH, b1 + l * DH, T1,
                                         NG_, NGpad, NTOT,
                                         nullptr, nullptr, nullptr, invNg, invNq, st1);
        tgemm_k<256, true><<<gg, 256>>>(T1, W2 + l * DH * DH, b2 + l * DH, T0,
                                        NG_, NGpad, NTOT,
                                        st1, bn1g + l * DH, bn1b + l * DH,
                                        invNg, invNq, stA);
        bnstats_k<<<GRID_EW, DH>>>(T0, stA, bnAg + l * DH, bnAb + l * DH, stG,
                                   invNg, invNq, NG_, NGpad, NTOT, SPLIT);
        bnresid_k<<<GRID_EW, DH>>>(T0, H, stA, bnAg + l * DH, bnAb + l * DH,
                                   stG, bnGg + l * DH, bnGb + l * DH,
                                   invNg, invNq, NG_, NGpad, NTOT, SPLIT);
    }
    int nbG = (NG_ + 63) / 64, nbQ = (NQ_ + 63) / 64;
    readout_k<<<nbG + nbQ, 256>>>(H, gid_g, gid_q, rd, NG_, NGpad, NQ_, nbG);

    predictor_k<<<NGR, DH>>>(rd, Wp1, bp1, Wp2, bp2, (float*)d_out);
}

// round 11
// speedup vs baseline: 1.5913x; 1.0739x over previous
#include <cuda_runtime.h>
#include <cuda_bf16.h>
#include <cstdint>

#define DH     256
#define NLAY   4
#define NGR    64
#define NTMAX  60160
#define EMAX   960000
#define BNEPS  1e-5f

// packed-weight offsets (u32 kpair-major [KP][256])
#define OFF_EMB 0
#define OFF_W1  16384
#define OFF_W2  147456
#define WPK_TOT 278528

// ---------------- scratch (static __device__ globals; no allocations) ----------------
__device__ float    g_H [NTMAX*DH];
__device__ float    g_T0[NTMAX*DH];
__device__ uint32_t g_P0H[NTMAX*128];
__device__ uint32_t g_P0L[NTMAX*128];
__device__ uint32_t g_P1H[NTMAX*128];
__device__ uint32_t g_P1L[NTMAX*128];
__device__ uint32_t g_WH[WPK_TOT];
__device__ uint32_t g_WL[WPK_TOT];
__device__ float    g_stats[NLAY*3*1024];
__device__ float    g_read[2*NGR*DH];
__device__ int      g_cnt [NTMAX];
__device__ int      g_wofs[NTMAX];
__device__ int      g_rowptr[NTMAX+1];
__device__ int      g_esrc[EMAX];
__device__ int      g_bsum[256];

// ---------------- helpers ----------------
__device__ __forceinline__ uint32_t pack_hi(float e, float o, float& re, float& ro) {
    __nv_bfloat16 he = __float2bfloat16(e);
    __nv_bfloat16 ho = __float2bfloat16(o);
    re = e - __bfloat162float(he);
    ro = o - __bfloat162float(ho);
    return (uint32_t)__bfloat16_as_ushort(he) | ((uint32_t)__bfloat16_as_ushort(ho) << 16);
}
__device__ __forceinline__ uint32_t pack_lo(float re, float ro) {
    __nv_bfloat16 le = __float2bfloat16(re);
    __nv_bfloat16 lo = __float2bfloat16(ro);
    return (uint32_t)__bfloat16_as_ushort(le) | ((uint32_t)__bfloat16_as_ushort(lo) << 16);
}
__device__ __forceinline__ float2 unpack2(uint32_t h, uint32_t l) {
    __nv_bfloat162 hb = *reinterpret_cast<const __nv_bfloat162*>(&h);
    __nv_bfloat162 lb = *reinterpret_cast<const __nv_bfloat162*>(&l);
    float2 hf = __bfloat1622float2(hb), lf = __bfloat1622float2(lb);
    return make_float2(hf.x + lf.x, hf.y + lf.y);
}
__device__ __forceinline__ void mma_bf16(float* d, const uint32_t* a, const uint32_t* b) {
    asm volatile("mma.sync.aligned.m16n8k16.row.col.f32.bf16.bf16.f32 "
        "{%0,%1,%2,%3}, {%4,%5,%6,%7}, {%8,%9}, {%0,%1,%2,%3};\n"
        : "+f"(d[0]), "+f"(d[1]), "+f"(d[2]), "+f"(d[3])
        : "r"(a[0]), "r"(a[1]), "r"(a[2]), "r"(a[3]), "r"(b[0]), "r"(b[1]));
}
__device__ __forceinline__ void cpa16(void* dst, const void* src, bool v) {
    uint32_t d = (uint32_t)__cvta_generic_to_shared(dst);
    int sz = v ? 16 : 0;
    asm volatile("cp.async.cg.shared.global [%0], [%1], 16, %2;"
                 :: "r"(d), "l"(src), "r"(sz));
}
__device__ __forceinline__ void bn_coeff(const float* st, const float* gamma,
                                         const float* beta, float invN, int c,
                                         float& sc, float& sh) {
    float m = st[c] * invN;
    float v = st[256 + c] * invN - m * m;
    sc = gamma[c] * rsqrtf(v + BNEPS);
    sh = fmaf(-m, sc, beta[c]);
}

// ---------------- small utility kernels ----------------
__global__ void zero_kernel(float* p, int n) {
    int i = blockIdx.x * blockDim.x + threadIdx.x;
    if (i < n) p[i] = 0.f;
}
__global__ void zeroi_kernel(int* p, int n) {
    int i = blockIdx.x * blockDim.x + threadIdx.x;
    if (i < n) p[i] = 0;
}

// ---------------- weight / input packing ----------------
__global__ void packW_k(const float* __restrict__ We, const float* __restrict__ W1,
                        const float* __restrict__ W2,
                        uint32_t* __restrict__ WH, uint32_t* __restrict__ WL) {
    int i = blockIdx.x * 256 + threadIdx.x;
    if (i >= WPK_TOT) return;
    const float* src; int p, n;
    if (i < OFF_W1) { src = We; p = i >> 8; n = i & 255; }
    else if (i < OFF_W2) { int j = i - OFF_W1; int l = j >> 15; j &= 32767;
                           src = W1 + l * 65536; p = j >> 8; n = j & 255; }
    else { int j = i - OFF_W2; int l = j >> 15; j &= 32767;
           src = W2 + l * 65536; p = j >> 8; n = j & 255; }
    float e = src[(2 * p) * 256 + n], o = src[(2 * p + 1) * 256 + n];
    float re, ro;
    WH[i] = pack_hi(e, o, re, ro);
    WL[i] = pack_lo(re, ro);
}

__global__ void packX_k(const float* __restrict__ X, const float* __restrict__ Xq,
                        uint32_t* __restrict__ PH, uint32_t* __restrict__ PL,
                        int NG, int NGpad, int NQ) {
    int i = blockIdx.x * 256 + threadIdx.x;
    int totG = NG * 64;
    if (i >= totG + NQ * 64) return;
    const float* src; int r, p, ro_;
    if (i < totG) { r = i >> 6; p = i & 63; src = X; ro_ = r; }
    else { int j = i - totG; r = j >> 6; p = j & 63; src = Xq; ro_ = NGpad + r; }
    float e = src[r * 128 + 2 * p], o = src[r * 128 + 2 * p + 1];
    float re, rr;
    PH[(long)ro_ * 64 + p] = pack_hi(e, o, re, rr);
    PL[(long)ro_ * 64 + p] = pack_lo(re, rr);
}

// ================= CSR build =================
__global__ void hist_k(const int* __restrict__ dst, int E, int* __restrict__ cnt, int off) {
    int i = blockIdx.x * blockDim.x + threadIdx.x;
    if (i < E) atomicAdd(&cnt[dst[i] + off], 1);
}
__global__ void blocksum_k(const int* __restrict__ cnt, int* __restrict__ bsum, int N) {
    __shared__ int sh[256];
    int i = blockIdx.x * 256 + threadIdx.x;
    sh[threadIdx.x] = (i < N) ? cnt[i] : 0;
    __syncthreads();
    for (int s = 128; s > 0; s >>= 1) {
        if (threadIdx.x < s) sh[threadIdx.x] += sh[threadIdx.x + s];
        __syncthreads();
    }
    if (threadIdx.x == 0) bsum[blockIdx.x] = sh[0];
}
__global__ void scanb_k(int* __restrict__ bsum, int nb) {
    __shared__ int sh[256];
    int t = threadIdx.x;
    sh[t] = (t < nb) ? bsum[t] : 0;
    __syncthreads();
    for (int off = 1; off < 256; off <<= 1) {
        int v = (t >= off) ? sh[t - off] : 0;
        __syncthreads();
        sh[t] += v;
        __syncthreads();
    }
    if (t < nb) bsum[t] = t ? sh[t - 1] : 0;
}
__global__ void scanfin_k(const int* __restrict__ cnt, const int* __restrict__ bpre,
                          int* __restrict__ rowptr, int* __restrict__ wofs, int N, int E) {
    __shared__ int sh[256];
    int i = blockIdx.x * 256 + threadIdx.x;
    int v = (i < N) ? cnt[i] : 0;
    sh[threadIdx.x] = v;
    __syncthreads();
    for (int off = 1; off < 256; off <<= 1) {
        int u = (threadIdx.x >= off) ? sh[threadIdx.x - off] : 0;
        __syncthreads();
        sh[threadIdx.x] += u;
        __syncthreads();
    }
    int excl = sh[threadIdx.x] - v + bpre[blockIdx.x];
    if (i < N) { rowptr[i] = excl; wofs[i] = excl; }
    if (blockIdx.x == 0 && threadIdx.x == 0) rowptr[N] = E;
}
__global__ void fill_k(const int* __restrict__ src, const int* __restrict__ dst, int E,
                       int* __restrict__ wofs, int* __restrict__ esrc, int off) {
    int i = blockIdx.x * blockDim.x + threadIdx.x;
    if (i < E) {
        int p = atomicAdd(&wofs[dst[i] + off], 1);
        esrc[p] = src[i] + off;
    }
}

// gather: out = (1+eps)*H[v] + sum H[src[e]]  -> packed hi/lo (stride 128 u32)
__global__ __launch_bounds__(256) void gather_k(
    const float* __restrict__ H, uint32_t* __restrict__ PH, uint32_t* __restrict__ PL,
    const int* __restrict__ rowptr, const int* __restrict__ esrc,
    const float* __restrict__ eps, int l, int N)
{
    int w    = (blockIdx.x * blockDim.x + threadIdx.x) >> 5;
    int lane = threadIdx.x & 31;
    if (w >= N) return;
    float e = 1.f + __ldg(&eps[l]);
    const float4* hr = (const float4*)(H + (long)w * DH);
    float4 a = hr[lane * 2], b = hr[lane * 2 + 1];
    a.x *= e; a.y *= e; a.z *= e; a.w *= e;
    b.x *= e; b.y *= e; b.z *= e; b.w *= e;
    int i0 = rowptr[w], i1 = rowptr[w + 1];
    for (int i = i0; i < i1; i++) {
        int s = __ldg(&esrc[i]);
        const float4* hs = (const float4*)(H + (long)s * DH);
        float4 u = hs[lane * 2], v = hs[lane * 2 + 1];
        a.x += u.x; a.y += u.y; a.z += u.z; a.w += u.w;
        b.x += v.x; b.y += v.y; b.z += v.z; b.w += v.w;
    }
    float re, ro;
    uint4 h4, l4;
    h4.x = pack_hi(a.x, a.y, re, ro); l4.x = pack_lo(re, ro);
    h4.y = pack_hi(a.z, a.w, re, ro); l4.y = pack_lo(re, ro);
    h4.z = pack_hi(b.x, b.y, re, ro); l4.z = pack_lo(re, ro);
    h4.w = pack_hi(b.z, b.w, re, ro); l4.w = pack_lo(re, ro);
    *(uint4*)&PH[(long)w * 128 + lane * 4] = h4;
    *(uint4*)&PL[(long)w * 128 + lane * 4] = l4;
}

// ================= GEMM 1: pure-copy staging, cp.async double-buffered =================
// C = A @ W + bias; A packed hi/lo [rows][KP], W packed [KP][256].
#define PK_SMEM 75776
template<int KP, bool PACK_OUT>
__global__ __launch_bounds__(256, 2) void tgemm_pk(
    const uint32_t* __restrict__ APH, const uint32_t* __restrict__ APL,
    const uint32_t* __restrict__ WPH, const uint32_t* __restrict__ WPL,
    const float* __restrict__ bias,
    float* __restrict__ Cf, uint32_t* __restrict__ CPH, uint32_t* __restrict__ CPL,
    int NG, int NGpad, int NTOT, float* __restrict__ stout)
{
    extern __shared__ uint32_t sm[];
    uint32_t (*AH)[128][20] = (uint32_t(*)[128][20])(sm);
    uint32_t (*AL)[128][20] = (uint32_t(*)[128][20])(sm + 5120);
    uint32_t (*BH)[16][136] = (uint32_t(*)[16][136])(sm + 10240);
    uint32_t (*BL)[16][136] = (uint32_t(*)[16][136])(sm + 14592);

    const int tid = threadIdx.x;
    const int wid = tid >> 5, lane = tid & 31;
    const int g = lane >> 2, tig = lane & 3;
    const int mrw = (wid & 1) * 64;
    const int nbw = (wid >> 1) * 32;
    const int mbase = blockIdx.x * 128;
    const int nbase = blockIdx.y * 128;
    const int graph = (mbase >= NGpad) ? 1 : 0;
    const int Mv = graph ? NTOT : NG;

    float acc[4][4][4] = {};

    const int ar = tid >> 1, akp = (tid & 1) * 8;
    const int bkp = tid >> 4, bn0 = (tid & 15) * 8;
    const int arow = mbase + ar;
    const bool av = (arow < NG) || (arow >= NGpad && arow < NTOT);
    const long abase = (long)arow * KP;
    constexpr int NT = KP / 16;

#define PK_ISSUE(tt, bf)                                                        \
    {                                                                           \
        int tkp = (tt) * 16;                                                    \
        cpa16(&AH[bf][ar][akp],     APH + abase + tkp + akp,     av);           \
        cpa16(&AH[bf][ar][akp + 4], APH + abase + tkp + akp + 4, av);           \
        cpa16(&AL[bf][ar][akp],     APL + abase + tkp + akp,     av);           \
        cpa16(&AL[bf][ar][akp + 4], APL + abase + tkp + akp + 4, av);           \
        const uint32_t* wh = WPH + (long)(tkp + bkp) * 256 + nbase + bn0;       \
        const uint32_t* wl = WPL + (long)(tkp + bkp) * 256 + nbase + bn0;       \
        cpa16(&BH[bf][bkp][bn0],     wh,     true);                             \
        cpa16(&BH[bf][bkp][bn0 + 4], wh + 4, true);                             \
        cpa16(&BL[bf][bkp][bn0],     wl,     true);                             \
        cpa16(&BL[bf][bkp][bn0 + 4], wl + 4, true);                             \
        asm volatile("cp.async.commit_group;");                                 \
    }

    PK_ISSUE(0, 0);
    for (int tt = 0; tt < NT; tt++) {
        asm volatile("cp.async.wait_group %0;" :: "n"(0));
        __syncthreads();
        if (tt + 1 < NT) PK_ISSUE(tt + 1, (tt + 1) & 1);
        const int b = tt & 1;
        #pragma unroll
        for (int c = 0; c < 2; c++) {
            uint32_t bh[4][2], bl[4][2];
            #pragma unroll
            for (int nf = 0; nf < 4; nf++) {
                int cn = nbw + nf * 8 + g;
                bh[nf][0] = BH[b][c * 8 + tig][cn];
                bh[nf][1] = BH[b][c * 8 + tig + 4][cn];
                bl[nf][0] = BL[b][c * 8 + tig][cn];
                bl[nf][1] = BL[b][c * 8 + tig + 4][cn];
            }
            #pragma unroll
            for (int mf = 0; mf < 4; mf++) {
                int r0 = mrw + mf * 16 + g;
                uint32_t ah[4], al_[4];
                ah[0] = AH[b][r0][c * 8 + tig];      ah[1] = AH[b][r0 + 8][c * 8 + tig];
                ah[2] = AH[b][r0][c * 8 + tig + 4];  ah[3] = AH[b][r0 + 8][c * 8 + tig + 4];
                al_[0] = AL[b][r0][c * 8 + tig];     al_[1] = AL[b][r0 + 8][c * 8 + tig];
                al_[2] = AL[b][r0][c * 8 + tig + 4]; al_[3] = AL[b][r0 + 8][c * 8 + tig + 4];
                #pragma unroll
                for (int nf = 0; nf < 4; nf++) {
                    mma_bf16(acc[mf][nf], ah,  bh[nf]);
                    mma_bf16(acc[mf][nf], ah,  bl[nf]);
                    mma_bf16(acc[mf][nf], al_, bh[nf]);
                }
            }
        }
    }
#undef PK_ISSUE

    // epilogue
    float s[4][2] = {}, q[4][2] = {};
    #pragma unroll
    for (int nf = 0; nf < 4; nf++) {
        int col = nbase + nbw + nf * 8 + 2 * tig;
        float2 bb = *(const float2*)&bias[col];
        #pragma unroll
        for (int mf = 0; mf < 4; mf++) {
            int r0 = mbase + mrw + mf * 16 + g;
            float v0 = acc[mf][nf][0] + bb.x, v1 = acc[mf][nf][1] + bb.y;
            float v2 = acc[mf][nf][2] + bb.x, v3 = acc[mf][nf][3] + bb.y;
            if (r0 < Mv) {
                if (PACK_OUT) {
                    float re, ro;
                    uint32_t ph = pack_hi(v0, v1, re, ro);
                    CPH[(long)r0 * 128 + (col >> 1)] = ph;
                    CPL[(long)r0 * 128 + (col >> 1)] = pack_lo(re, ro);
                } else {
                    float2 o = {v0, v1};
                    *(float2*)&Cf[(long)r0 * DH + col] = o;
                }
                s[nf][0] += v0; s[nf][1] += v1;
                q[nf][0] += v0 * v0; q[nf][1] += v1 * v1;
            }
            if (r0 + 8 < Mv) {
                if (PACK_OUT) {
                    float re, ro;
                    uint32_t ph = pack_hi(v2, v3, re, ro);
                    CPH[(long)(r0 + 8) * 128 + (col >> 1)] = ph;
                    CPL[(long)(r0 + 8) * 128 + (col >> 1)] = pack_lo(re, ro);
                } else {
                    float2 o = {v2, v3};
                    *(float2*)&Cf[(long)(r0 + 8) * DH + col] = o;
                }
                s[nf][0] += v2; s[nf][1] += v3;
                q[nf][0] += v2 * v2; q[nf][1] += v3 * v3;
            }
        }
    }
    if (stout) {
        float* st = stout + graph * 512;
        #pragma unroll
        for (int nf = 0; nf < 4; nf++)
            #pragma unroll
            for (int c2 = 0; c2 < 2; c2++) {
                float ss = s[nf][c2], qq = q[nf][c2];
                ss += __shfl_xor_sync(0xffffffffu, ss, 4);
                ss += __shfl_xor_sync(0xffffffffu, ss, 8);
                ss += __shfl_xor_sync(0xffffffffu, ss, 16);
                qq += __shfl_xor_sync(0xffffffffu, qq, 4);
                qq += __shfl_xor_sync(0xffffffffu, qq, 8);
                qq += __shfl_xor_sync(0xffffffffu, qq, 16);
                if (lane < 4) {
                    int col = nbase + nbw + nf * 8 + 2 * tig + c2;
                    atomicAdd(&st[col], ss);
                    atomicAdd(&st[256 + col], qq);
                }
            }
    }
}

// ================= GEMM 2: A = relu(bn(hi+lo)) re-split inline; B pre-packed =================
__global__ __launch_bounds__(256, 2) void tgemm_tr(
    const uint32_t* __restrict__ APH, const uint32_t* __restrict__ APL,
    const uint32_t* __restrict__ WPH, const uint32_t* __restrict__ WPL,
    const float* __restrict__ bias, float* __restrict__ Cf,
    int NG, int NGpad, int NTOT,
    const float* __restrict__ stin, const float* __restrict__ gamma,
    const float* __restrict__ beta, float invNg, float invNq,
    float* __restrict__ stout)
{
    __shared__ uint32_t AH[128][20], AL[128][20];
    __shared__ uint32_t BH[16][136], BL[16][136];
    __shared__ float sSc[256], sSh[256];

    const int tid = threadIdx.x;
    const int wid = tid >> 5, lane = tid & 31;
    const int g = lane >> 2, tig = lane & 3;
    const int mrw = (wid & 1) * 64;
    const int nbw = (wid >> 1) * 32;
    const int mbase = blockIdx.x * 128;
    const int nbase = blockIdx.y * 128;
    const int graph = (mbase >= NGpad) ? 1 : 0;
    const int Mv = graph ? NTOT : NG;

    {
        float sc, sh;
        bn_coeff(stin + graph * 512, gamma, beta, graph ? invNq : invNg, tid, sc, sh);
        sSc[tid] = sc; sSh[tid] = sh;
        __syncthreads();
    }

    float acc[4][4][4] = {};
    const int ar = tid >> 1, akp = (tid & 1) * 8;
    const int bkp = tid >> 4, bn0 = (tid & 15) * 8;
    const int arow = mbase + ar;
    const bool av = (arow < NG) || (arow >= NGpad && arow < NTOT);
    const long abase = (long)arow * 128;

    for (int tt = 0; tt < 8; tt++) {
        int tkp = tt * 16;
        // A: load packed, reconstruct, BN+ReLU, re-split
        {
            uint32_t hv[8] = {}, lv[8] = {};
            if (av) {
                *(uint4*)&hv[0] = *(const uint4*)&APH[abase + tkp + akp];
                *(uint4*)&hv[4] = *(const uint4*)&APH[abase + tkp + akp + 4];
                *(uint4*)&lv[0] = *(const uint4*)&APL[abase + tkp + akp];
                *(uint4*)&lv[4] = *(const uint4*)&APL[abase + tkp + akp + 4];
            }
            #pragma unroll
            for (int j = 0; j < 8; j++) {
                float2 x = unpack2(hv[j], lv[j]);
                int ks = tt * 32 + (akp + j) * 2;
                x.x = fmaxf(fmaf(x.x, sSc[ks], sSh[ks]), 0.f);
                x.y = fmaxf(fmaf(x.y, sSc[ks + 1], sSh[ks + 1]), 0.f);
                float re, ro;
                AH[ar][akp + j] = pack_hi(x.x, x.y, re, ro);
                AL[ar][akp + j] = pack_lo(re, ro);
            }
        }
        // B: pure copy
        {
            const uint32_t* wh = WPH + (long)(tkp + bkp) * 256 + nbase + bn0;
            const uint32_t* wl = WPL + (long)(tkp + bkp) * 256 + nbase + bn0;
            *(uint4*)&BH[bkp][bn0]     = *(const uint4*)wh;
            *(uint4*)&BH[bkp][bn0 + 4] = *(const uint4*)(wh + 4);
            *(uint4*)&BL[bkp][bn0]     = *(const uint4*)wl;
            *(uint4*)&BL[bkp][bn0 + 4] = *(const uint4*)(wl + 4);
        }
        __syncthreads();

        #pragma unroll
        for (int c = 0; c < 2; c++) {
            uint32_t bh[4][2], bl[4][2];
            #pragma unroll
            for (int nf = 0; nf < 4; nf++) {
                int cn = nbw + nf * 8 + g;
                bh[nf][0] = BH[c * 8 + tig][cn];
                bh[nf][1] = BH[c * 8 + tig + 4][cn];
                bl[nf][0] = BL[c * 8 + tig][cn];
                bl[nf][1] = BL[c * 8 + tig + 4][cn];
            }
            #pragma unroll
            for (int mf = 0; mf < 4; mf++) {
                int r0 = mrw + mf * 16 + g;
                uint32_t ah[4], al_[4];
                ah[0] = AH[r0][c * 8 + tig];      ah[1] = AH[r0 + 8][c * 8 + tig];
                ah[2] = AH[r0][c * 8 + tig + 4];  ah[3] = AH[r0 + 8][c * 8 + tig + 4];
                al_[0] = AL[r0][c * 8 + tig];     al_[1] = AL[r0 + 8][c * 8 + tig];
                al_[2] = AL[r0][c * 8 + tig + 4]; al_[3] = AL[r0 + 8][c * 8 + tig + 4];
                #pragma unroll
                for (int nf = 0; nf < 4; nf++) {
                    mma_bf16(acc[mf][nf], ah,  bh[nf]);
                    mma_bf16(acc[mf][nf], ah,  bl[nf]);
                    mma_bf16(acc[mf][nf], al_, bh[nf]);
                }
            }
        }
        __syncthreads();
    }

    // epilogue: f32 out + stats
    float s[4][2] = {}, q[4][2] = {};
    #pragma unroll
    for (int nf = 0; nf < 4; nf++) {
        int col = nbase + nbw + nf * 8 + 2 * tig;
        float2 bb = *(const float2*)&bias[col];
        #pragma unroll
        for (int mf = 0; mf < 4; mf++) {
            int r0 = mbase + mrw + mf * 16 + g;
            float v0 = acc[mf][nf][0] + bb.x, v1 = acc[mf][nf][1] + bb.y;
            float v2 = acc[mf][nf][2] + bb.x, v3 = acc[mf][nf][3] + bb.y;
            if (r0 < Mv) {
                float2 o = {v0, v1};
                *(float2*)&Cf[(long)r0 * DH + col] = o;
                s[nf][0] += v0; s[nf][1] += v1;
                q[nf][0] += v0 * v0; q[nf][1] += v1 * v1;
            }
            if (r0 + 8 < Mv) {
                float2 o = {v2, v3};
                *(float2*)&Cf[(long)(r0 + 8) * DH + col] = o;
                s[nf][0] += v2; s[nf][1] += v3;
                q[nf][0] += v2 * v2; q[nf][1] += v3 * v3;
            }
        }
    }
    {
        float* st = stout + graph * 512;
        #pragma unroll
        for (int nf = 0; nf < 4; nf++)
            #pragma unroll
            for (int c2 = 0; c2 < 2; c2++) {
                float ss = s[nf][c2], qq = q[nf][c2];
                ss += __shfl_xor_sync(0xffffffffu, ss, 4);
                ss += __shfl_xor_sync(0xffffffffu, ss, 8);
                ss += __shfl_xor_sync(0xffffffffu, ss, 16);
                qq += __shfl_xor_sync(0xffffffffu, qq, 4);
                qq += __shfl_xor_sync(0xffffffffu, qq, 8);
                qq += __shfl_xor_sync(0xffffffffu, qq, 16);
                if (lane < 4) {
                    int col = nbase + nbw + nf * 8 + 2 * tig + c2;
                    atomicAdd(&st[col], ss);
                    atomicAdd(&st[256 + col], qq);
                }
            }
    }
}

// ---------------- elementwise stages ----------------
__global__ void bnstats_k(const float* __restrict__ T0,
                          const float* __restrict__ stA, const float* __restrict__ gA,
                          const float* __restrict__ bA, float* __restrict__ stG,
                          float invNg, float invNq,
                          int NG, int NGpad, int NTOT, int split) {
    int c = threadIdx.x, b = blockIdx.x;
    int graph, r0, r1;
    if (b < split) {
        graph = 0; int rpb = (NG + split - 1) / split;
        r0 = b * rpb; r1 = min(NG, r0 + rpb);
    } else {
        graph = 1; int nb = gridDim.x - split, bb = b - split;
        int nq = NTOT - NGpad; int rpb = (nq + nb - 1) / nb;
        r0 = NGpad + bb * rpb; r1 = min(NTOT, r0 + rpb);
    }
    float scA, shA;
    bn_coeff(stA + graph * 512, gA, bA, graph ? invNq : invNg, c, scA, shA);
    float s = 0.f, q = 0.f;
    for (int r = r0; r < r1; r++) {
        float v = fmaxf(fmaf(T0[(long)r * DH + c], scA, shA), 0.f);
        s += v; q += v * v;
    }
    atomicAdd(&stG[graph * 512 + c], s);
    atomicAdd(&stG[graph * 512 + 256 + c], q);
}

__global__ void bnresid_k(const float* __restrict__ T0, float* __restrict__ H,
                          const float* __restrict__ stA, const float* __restrict__ gA,
                          const float* __restrict__ bA,
                          const float* __restrict__ stG, const float* __restrict__ gG,
                          const float* __restrict__ bG,
                          float invNg, float invNq,
                          int NG, int NGpad, int NTOT, int split) {
    int c = threadIdx.x, b = blockIdx.x;
    int graph, r0, r1;
    if (b < split) {
        graph = 0; int rpb = (NG + split - 1) / split;
        r0 = b * rpb; r1 = min(NG, r0 + rpb);
    } else {
        graph = 1; int nb = gridDim.x - split, bb = b - split;
        int nq = NTOT - NGpad; int rpb = (nq + nb - 1) / nb;
        r0 = NGpad + bb * rpb; r1 = min(NTOT, r0 + rpb);
    }
    float invN = graph ? invNq : invNg;
    float scA, shA, scG, shG;
    bn_coeff(stA + graph * 512, gA, bA, invN, c, scA, shA);
    bn_coeff(stG + graph * 512, gG, bG, invN, c, scG, shG);
    for (int r = r0; r < r1; r++) {
        long idx = (long)r * DH + c;
        float v = fmaxf(fmaf(T0[idx], scA, shA), 0.f);
        H[idx] += fmaxf(fmaf(v, scG, shG), 0.f);
    }
}

// ---------------- readout + predictor ----------------
__global__ void readout_k(const float* __restrict__ H,
                          const int* __restrict__ gidg, const int* __restrict__ gidq,
                          float* __restrict__ rd, int NG, int NGpad, int NQ, int nbG) {
    int c = threadIdx.x, b = blockIdx.x;
    const float* Hp; const int* gid; float* out; int r0, M;
    if (b < nbG) { Hp = H; gid = gidg; out = rd; r0 = b * 64; M = NG; }
    else { Hp = H + (long)NGpad * DH; gid = gidq; out = rd + NGR * DH;
           r0 = (b - nbG) * 64; M = NQ; }
    if (r0 >= M) return;
    int r1 = min(M, r0 + 64);
    int cur = gid[r0];
    float acc = 0.f;
    for (int r = r0; r < r1; r++) {
        int g = gid[r];
        if (g != cur) { atomicAdd(&out[cur * DH + c], acc); acc = 0.f; cur = g; }
        acc += Hp[(long)r * DH + c];
    }
    atomicAdd(&out[cur * DH + c], acc);
}

__global__ void predictor_k(const float* __restrict__ rd, const float* __restrict__ Wp1,
                            const float* __restrict__ bp1, const float* __restrict__ Wp2,
                            const float* __restrict__ bp2, float* __restrict__ out) {
    __shared__ float dvec[DH];
    __shared__ float hred[DH];
    int g = blockIdx.x, t = threadIdx.x;
    dvec[t] = fabsf(rd[g * DH + t] - rd[NGR * DH + g * DH + t]);
    __syncthreads();
    float acc = bp1[t];
    for (int k = 0; k < DH; k++) acc = fmaf(dvec[k], Wp1[k * DH + t], acc);
    hred[t] = fmaxf(acc, 0.f) * Wp2[t];
    __syncthreads();
    for (int s = DH / 2; s > 0; s >>= 1) {
        if (t < s) hred[t] += hred[t + s];
        __syncthreads();
    }
    if (t == 0) out[g] = hred[0] + bp2[0];
}

extern "C" void kernel_launch(void* const* d_in, const int* in_sizes, int n_in,
                              void* d_out, int out_size) {
    const float* X     = (const float*)d_in[0];
    const float* Xq    = (const float*)d_in[2];
    const float* W_emb = (const float*)d_in[4];
    const float* b_emb = (const float*)d_in[5];
    const float* eps   = (const float*)d_in[6];
    const float* W1    = (const float*)d_in[7];
    const float* b1    = (const float*)d_in[8];
    const float* bn1g  = (const float*)d_in[9];
    const float* bn1b  = (const float*)d_in[10];
    const float* W2    = (const float*)d_in[11];
    const float* b2    = (const float*)d_in[12];
    const float* bnAg  = (const float*)d_in[13];
    const float* bnAb  = (const float*)d_in[14];
    const float* bnGg  = (const float*)d_in[15];
    const float* bnGb  = (const float*)d_in[16];
    const float* Wp1   = (const float*)d_in[17];
    const float* bp1   = (const float*)d_in[18];
    const float* Wp2   = (const float*)d_in[19];
    const float* bp2   = (const float*)d_in[20];
    const int* src_g   = (const int*)d_in[21];
    const int* dst_g   = (const int*)d_in[22];
    const int* gid_g   = (const int*)d_in[23];
    const int* src_q   = (const int*)d_in[24];
    const int* dst_q   = (const int*)d_in[25];
    const int* gid_q   = (const int*)d_in[26];

    int NG_ = in_sizes[0] / 128;
    int NQ_ = in_sizes[2] / 128;
    int EG_ = in_sizes[21];
    int EQ_ = in_sizes[24];
    int NGpad = ((NG_ + 127) / 128) * 128;
    int NTOT  = NGpad + NQ_;
    int Etot  = EG_ + EQ_;

    float *H, *T0, *stats, *rd;
    uint32_t *P0H, *P0L, *P1H, *P1L, *WH, *WL;
    int *cnt, *wofs, *rowptr, *esrc, *bsum;
    cudaGetSymbolAddress((void**)&H,      g_H);
    cudaGetSymbolAddress((void**)&T0,     g_T0);
    cudaGetSymbolAddress((void**)&P0H,    g_P0H);
    cudaGetSymbolAddress((void**)&P0L,    g_P0L);
    cudaGetSymbolAddress((void**)&P1H,    g_P1H);
    cudaGetSymbolAddress((void**)&P1L,    g_P1L);
    cudaGetSymbolAddress((void**)&WH,     g_WH);
    cudaGetSymbolAddress((void**)&WL,     g_WL);
    cudaGetSymbolAddress((void**)&stats,  g_stats);
    cudaGetSymbolAddress((void**)&rd,     g_read);
    cudaGetSymbolAddress((void**)&cnt,    g_cnt);
    cudaGetSymbolAddress((void**)&wofs,   g_wofs);
    cudaGetSymbolAddress((void**)&rowptr, g_rowptr);
    cudaGetSymbolAddress((void**)&esrc,   g_esrc);
    cudaGetSymbolAddress((void**)&bsum,   g_bsum);

    cudaFuncSetAttribute(tgemm_pk<64,  false>, cudaFuncAttributeMaxDynamicSharedMemorySize, PK_SMEM);
    cudaFuncSetAttribute(tgemm_pk<128, true>,  cudaFuncAttributeMaxDynamicSharedMemorySize, PK_SMEM);

    // pack weights + inputs
    packW_k<<<(WPK_TOT + 255) / 256, 256>>>(W_emb, W1, W2, WH, WL);
    packX_k<<<(((NG_ + NQ_) * 64) + 255) / 256, 256>>>(X, Xq, P0H, P0L, NG_, NGpad, NQ_);

    // combined CSR
    int nb = (NTOT + 255) / 256;
    zeroi_kernel<<<nb, 256>>>(cnt, NTOT);
    hist_k<<<(EG_ + 255) / 256, 256>>>(dst_g, EG_, cnt, 0);
    hist_k<<<(EQ_ + 255) / 256, 256>>>(dst_q, EQ_, cnt, NGpad);
    blocksum_k<<<nb, 256>>>(cnt, bsum, NTOT);
    scanb_k<<<1, 256>>>(bsum, nb);
    scanfin_k<<<nb, 256>>>(cnt, bsum, rowptr, wofs, NTOT, Etot);
    fill_k<<<(EG_ + 255) / 256, 256>>>(src_g, dst_g, EG_, wofs, esrc, 0);
    fill_k<<<(EQ_ + 255) / 256, 256>>>(src_q, dst_q, EQ_, wofs, esrc, NGpad);

    zero_kernel<<<(NLAY * 3 * 1024 + 255) / 256, 256>>>(stats, NLAY * 3 * 1024);
    zero_kernel<<<(2 * NGR * DH + 255) / 256, 256>>>(rd, 2 * NGR * DH);

    float invNg = 1.f / (float)NG_, invNq = 1.f / (float)NQ_;
    dim3 gg((NTOT + 127) / 128, 2);
    const int SPLIT = 512, GRID_EW = 640;

    // embedding GEMMs (packed X, KP=64)
    dim3 gge(NGpad / 128, 2), ggq((NQ_ + 127) / 128, 2);
    tgemm_pk<64, false><<<gge, 256, PK_SMEM>>>(P0H, P0L, WH + OFF_EMB, WL + OFF_EMB,
                                               b_emb, H, nullptr, nullptr,
                                               NG_, 1 << 30, NG_, nullptr);
    tgemm_pk<64, false><<<ggq, 256, PK_SMEM>>>(P0H + (long)NGpad * 64, P0L + (long)NGpad * 64,
                                               WH + OFF_EMB, WL + OFF_EMB,
                                               b_emb, H + (long)NGpad * DH, nullptr, nullptr,
                                               NQ_, 1 << 30, NQ_, nullptr);

    for (int l = 0; l < NLAY; l++) {
        float* st1 = stats + (l * 3 + 0) * 1024;
        float* stA = stats + (l * 3 + 1) * 1024;
        float* stG = stats + (l * 3 + 2) * 1024;
        gather_k<<<(NTOT + 7) / 8, 256>>>(H, P0H, P0L, rowptr, esrc, eps, l, NTOT);
        tgemm_pk<128, true><<<gg, 256, PK_SMEM>>>(P0H, P0L,
                                                  WH + OFF_W1 + l * 32768, WL + OFF_W1 + l * 32768,
                                                  b1 + l * DH, nullptr, P1H, P1L,
                                                  NG_, NGpad, NTOT, st1);
        tgemm_tr<<<gg, 256>>>(P1H, P1L,
                              WH + OFF_W2 + l * 32768, WL + OFF_W2 + l * 32768,
                              b2 + l * DH, T0, NG_, NGpad, NTOT,
                              st1, bn1g + l * DH, bn1b + l * DH, invNg, invNq, stA);
        bnstats_k<<<GRID_EW, DH>>>(T0, stA, bnAg + l * DH, bnAb + l * DH, stG,
                                   invNg, invNq, NG_, NGpad, NTOT, SPLIT);
        bnresid_k<<<GRID_EW, DH>>>(T0, H, stA, bnAg + l * DH, bnAb + l * DH,
                                   stG, bnGg + l * DH, bnGb + l * DH,
                                   invNg, invNq, NG_, NGpad, NTOT, SPLIT);
    }
    int nbG = (NG_ + 63) / 64, nbQ = (NQ_ + 63) / 64;
    readout_k<<<nbG + nbQ, 256>>>(H, gid_g, gid_q, rd, NG_, NGpad, NQ_, nbG);

    predictor_k<<<NGR, DH>>>(rd, Wp1, bp1, Wp2, bp2, (float*)d_out);
}